// round 15
// baseline (speedup 1.0000x reference)
#include <cuda_runtime.h>
#include <cuda_bf16.h>
#include <cuda_fp16.h>
#include <cstdint>

#define H   16
#define S   1024
#define D   64
#define HID 1024
#define BB  2
#define KPOS 512   /* 2K */
#define SCALE 0.07216878364870323f  /* 1/sqrt(64*3) */

// ---------------- scratch (static device memory; no allocation) ----------------
__device__ float g_V[BB*H*S*D];                 // fp32 V (transpose_v input)
__device__ unsigned short g_hidsp[BB*S*2048];   // [row][1024 hi | 1024 lo]
__device__ unsigned short g_relsp[KPOS*2048];
__device__ unsigned short g_Wsp[3*HID*2048];    // Wq | Wk | Wv
__device__ unsigned short g_Qsp[BB*H*S*128];    // [bh*1024+s][64 hi | 64 lo]
__device__ unsigned short g_Ksp[BB*H*S*128];
__device__ unsigned short g_posKsp[H*KPOS*128];
__device__ unsigned short g_posQsp[H*KPOS*128];
__device__ unsigned short g_Vtsp[BB*H*64*2048]; // [bh][d][1024 hi | 1024 lo]
__device__ __half g_c2pH[BB*H*S*KPOS];
__device__ __half g_p2cH[BB*H*S*KPOS];
__device__ short g_lutC[2048];
__device__ short g_lutP[2048];

__device__ __forceinline__ uint32_t smem_u32(const void* p) {
    uint32_t a;
    asm("{ .reg .u64 t; cvta.to.shared.u64 t, %1; cvt.u32.u64 %0, t; }" : "=r"(a) : "l"(p));
    return a;
}

#define CP_ASYNC16(dst, src) \
    asm volatile("cp.async.cg.shared.global [%0], [%1], 16;" :: "r"(dst), "l"(src))
#define CP_COMMIT()  asm volatile("cp.async.commit_group;" ::: "memory")
#define CP_WAIT0()   asm volatile("cp.async.wait_group 0;"  ::: "memory")
#define CP_WAIT1()   asm volatile("cp.async.wait_group 1;"  ::: "memory")

#define LDMATRIX_X4(r0, r1, r2, r3, addr) \
    asm volatile("ldmatrix.sync.aligned.m8n8.x4.shared.b16 {%0,%1,%2,%3}, [%4];" \
        : "=r"(r0), "=r"(r1), "=r"(r2), "=r"(r3) : "r"(addr))

#define MMA_BF16(c, a, b) \
    asm volatile("mma.sync.aligned.m16n8k16.row.col.f32.bf16.bf16.f32 " \
        "{%0,%1,%2,%3}, {%4,%5,%6,%7}, {%8,%9}, {%0,%1,%2,%3};" \
        : "+f"((c)[0]), "+f"((c)[1]), "+f"((c)[2]), "+f"((c)[3]) \
        : "r"((a)[0]), "r"((a)[1]), "r"((a)[2]), "r"((a)[3]), "r"((b)[0]), "r"((b)[1]))

__device__ __forceinline__ void split2(float x, float y, uint32_t& hi, uint32_t& lo) {
    __nv_bfloat16 hx = __float2bfloat16(x);
    __nv_bfloat16 hy = __float2bfloat16(y);
    __nv_bfloat16 lx = __float2bfloat16(x - __bfloat162float(hx));
    __nv_bfloat16 ly = __float2bfloat16(y - __bfloat162float(hy));
    hi = ((uint32_t)__bfloat16_as_ushort(hy) << 16) | __bfloat16_as_ushort(hx);
    lo = ((uint32_t)__bfloat16_as_ushort(ly) << 16) | __bfloat16_as_ushort(lx);
}

// ---------------- prep: split fp32 [rows][1024] -> [rows][1024 hi | 1024 lo] ---
__global__ void split_wide(const float* __restrict__ src, unsigned short* __restrict__ dst)
{
    int f4 = blockIdx.x * 256 + threadIdx.x;
    int row = f4 >> 8, c4 = (f4 & 255) * 4;
    float4 v = *(const float4*)(src + (size_t)f4 * 4);
    uint32_t h0, l0, h1, l1;
    split2(v.x, v.y, h0, l0);
    split2(v.z, v.w, h1, l1);
    unsigned short* r = dst + (size_t)row * 2048;
    *(uint2*)(r + c4)        = make_uint2(h0, h1);
    *(uint2*)(r + 1024 + c4) = make_uint2(l0, l1);
}

__global__ void split_w3(const float* __restrict__ Wq, const float* __restrict__ Wk,
                         const float* __restrict__ Wv)
{
    int row = blockIdx.x;              // 0..3071
    int which = row >> 10, lr = row & 1023;
    const float* src = (which==0) ? Wq : ((which==1) ? Wk : Wv);
    int c4 = threadIdx.x * 4;
    float4 v = *(const float4*)(src + (size_t)lr * 1024 + c4);
    uint32_t h0, l0, h1, l1;
    split2(v.x, v.y, h0, l0);
    split2(v.z, v.w, h1, l1);
    unsigned short* r = g_Wsp + (size_t)row * 2048;
    *(uint2*)(r + c4)        = make_uint2(h0, h1);
    *(uint2*)(r + 1024 + c4) = make_uint2(l0, l1);
}

// ---------------- gemm_bf16: 2-stage cp.async pipeline, 2 CTAs/SM --------------
// SAFE wait order: issue kt+1 BEFORE WAIT1 so "≤1 outstanding" proves group kt
// has fully landed (groups retire in order).
#define GB_STAGE 40960            /* AH 10240 | AL 10240 | BH 10240 | BL 10240 */
#define GB_SMEM  (2*GB_STAGE)

__global__ void __launch_bounds__(256, 2) gemm_bf16(
    const float* __restrict__ bq, const float* __restrict__ bk,
    const float* __restrict__ bv, int mode)
{
    extern __shared__ char sm[];
    int z = blockIdx.z;
    const unsigned short *A, *B;
    const float* bias = 0;
    __half* dstH = 0;
    int rsA, loffA, rsB, loffB, KT;
    if (mode == 0) {
        A = g_hidsp;                        rsA = 2048; loffA = 1024;
        B = g_Wsp + (size_t)z*HID*2048;     rsB = 2048; loffB = 1024;
        bias = (z==0) ? bq : ((z==1) ? bk : bv);
        KT = 32;
    } else if (mode == 1) {
        A = g_relsp;                        rsA = 2048; loffA = 1024;
        B = g_Wsp + (size_t)(z ? 0 : 1)*HID*2048;  rsB = 2048; loffB = 1024;
        bias = z ? bq : bk;
        KT = 32;
    } else {
        int sel = z >> 5, bh = z & 31, h = bh & 15;
        A = (sel ? g_Ksp : g_Qsp) + (size_t)bh*1024*128;   rsA = 128; loffA = 64;
        B = (sel ? g_posQsp : g_posKsp) + (size_t)h*512*128; rsB = 128; loffB = 64;
        dstH = (sel ? g_p2cH : g_c2pH) + (size_t)bh * S * KPOS;
        KT = 2;
    }

    int m0 = blockIdx.x * 128, n0 = blockIdx.y * 128;
    int t = threadIdx.x, wid = t >> 5, lid = t & 31;
    int wm = wid & 1, wn = wid >> 1;

    float c[4][4][4];
    #pragma unroll
    for (int i = 0; i < 4; i++)
        #pragma unroll
        for (int j = 0; j < 4; j++)
            #pragma unroll
            for (int r = 0; r < 4; r++) c[i][j][r] = 0.f;

    int rowA  = (lid & 7) + ((lid >> 3) & 1) * 8;
    int koffA = ((lid >> 4) & 1) * 16;
    int rowB  = (lid & 7) + ((lid >> 4) & 1) * 8;
    int koffB = ((lid >> 3) & 1) * 16;

    #define G_ISSUE(stage, kt) do { \
        uint32_t sbase = smem_u32(sm) + (stage) * GB_STAGE; \
        _Pragma("unroll") \
        for (int q = 0; q < 4; q++) { \
            int idx = t + 256*q, row = idx >> 3, cch = idx & 7; \
            int part = cch >> 2, ch = cch & 3; \
            const unsigned short* srcA = A + (size_t)(m0+row)*rsA + part*loffA + (kt)*32 + ch*8; \
            CP_ASYNC16(sbase + part*10240 + row*80 + ch*16, srcA); \
            const unsigned short* srcB = B + (size_t)(n0+row)*rsB + part*loffB + (kt)*32 + ch*8; \
            CP_ASYNC16(sbase + 20480 + part*10240 + row*80 + ch*16, srcB); \
        } \
        CP_COMMIT(); \
    } while (0)

    G_ISSUE(0, 0);

    for (int kt = 0; kt < KT; kt++) {
        if (kt + 1 < KT) { G_ISSUE((kt + 1) & 1, kt + 1); CP_WAIT1(); }
        else             { CP_WAIT0(); }
        __syncthreads();

        uint32_t aH = smem_u32(sm) + (kt & 1) * GB_STAGE;
        uint32_t aL = aH + 10240, bH = aH + 20480, bL = aH + 30720;

        #pragma unroll
        for (int s = 0; s < 2; s++) {
            uint32_t ah[4][4], al[4][4], bh[2][4], bl[2][4];
            #pragma unroll
            for (int mt = 0; mt < 4; mt++) {
                uint32_t ro = (uint32_t)((wm*64 + mt*16 + rowA) * 80 + s*32 + koffA);
                LDMATRIX_X4(ah[mt][0], ah[mt][1], ah[mt][2], ah[mt][3], aH + ro);
                LDMATRIX_X4(al[mt][0], al[mt][1], al[mt][2], al[mt][3], aL + ro);
            }
            #pragma unroll
            for (int q = 0; q < 2; q++) {
                uint32_t ro = (uint32_t)((wn*32 + q*16 + rowB) * 80 + s*32 + koffB);
                LDMATRIX_X4(bh[q][0], bh[q][1], bh[q][2], bh[q][3], bH + ro);
                LDMATRIX_X4(bl[q][0], bl[q][1], bl[q][2], bl[q][3], bL + ro);
            }
            #pragma unroll
            for (int mt = 0; mt < 4; mt++) {
                #pragma unroll
                for (int nt = 0; nt < 4; nt++) {
                    uint32_t bhf[2] = { bh[nt>>1][(nt&1)*2], bh[nt>>1][(nt&1)*2+1] };
                    uint32_t blf[2] = { bl[nt>>1][(nt&1)*2], bl[nt>>1][(nt&1)*2+1] };
                    MMA_BF16(c[mt][nt], ah[mt], bhf);
                    MMA_BF16(c[mt][nt], ah[mt], blf);
                    MMA_BF16(c[mt][nt], al[mt], bhf);
                }
            }
        }
        // protect buffer kt&1 before iteration kt+1 issues kt+2 into it
        if (kt + 2 < KT) __syncthreads();
    }

    // ---- epilogue ----
    #pragma unroll
    for (int mt = 0; mt < 4; mt++) {
        #pragma unroll
        for (int nt = 0; nt < 4; nt++) {
            int m = m0 + wm*64 + mt*16 + (lid >> 2);
            int n = n0 + wn*32 + nt*8  + 2*(lid & 3);
            float2 v0 = make_float2(c[mt][nt][0], c[mt][nt][1]);
            float2 v1 = make_float2(c[mt][nt][2], c[mt][nt][3]);
            if (mode == 2) {
                *(__half2*)(dstH + (size_t)m     * KPOS + n) =
                    __floats2half2_rn(v0.x*SCALE, v0.y*SCALE);
                *(__half2*)(dstH + (size_t)(m+8) * KPOS + n) =
                    __floats2half2_rn(v1.x*SCALE, v1.y*SCALE);
            } else {
                float2 bb = *(const float2*)(bias + n);
                v0.x += bb.x; v0.y += bb.y; v1.x += bb.x; v1.y += bb.y;
                int hh = n >> 6, dd = n & 63;
                if (mode == 0 && z == 2) {
                    int b = m >> 10, s2 = m & 1023;
                    size_t bse = ((((size_t)b * H + hh) * S + s2) << 6) + dd;
                    *(float2*)(g_V + bse) = v0;
                    *(float2*)(g_V + bse + (8u << 6)) = v1;
                } else {
                    unsigned short* dstp;
                    size_t r0, r1;
                    if (mode == 0) {
                        int b = m >> 10, s2 = m & 1023;
                        int bh2 = b * H + hh;
                        dstp = z ? g_Ksp : g_Qsp;
                        r0 = ((size_t)(bh2*1024 + s2))     << 7;
                        r1 = ((size_t)(bh2*1024 + s2 + 8)) << 7;
                    } else {
                        dstp = z ? g_posQsp : g_posKsp;
                        r0 = ((size_t)(hh*512 + m))     << 7;
                        r1 = ((size_t)(hh*512 + m + 8)) << 7;
                    }
                    uint32_t h0, l0;
                    split2(v0.x, v0.y, h0, l0);
                    *(uint32_t*)(dstp + r0 + dd)      = h0;
                    *(uint32_t*)(dstp + r0 + 64 + dd) = l0;
                    split2(v1.x, v1.y, h0, l0);
                    *(uint32_t*)(dstp + r1 + dd)      = h0;
                    *(uint32_t*)(dstp + r1 + 64 + dd) = l0;
                }
            }
        }
    }
    #undef G_ISSUE
}

// ---------------- transpose+split V ----------------
__global__ void transpose_v()
{
    __shared__ float sm[32][33];
    int bh = blockIdx.z;
    int j0 = blockIdx.x * 32, d0 = blockIdx.y * 32;
    int tx = threadIdx.x, ty = threadIdx.y;
    sm[ty][tx] = g_V[(size_t)bh*65536 + (size_t)(j0+ty)*64 + d0+tx];
    __syncthreads();
    float val = sm[tx][ty];
    __nv_bfloat16 hb = __float2bfloat16(val);
    __nv_bfloat16 lb = __float2bfloat16(val - __bfloat162float(hb));
    unsigned short* dr = g_Vtsp + (size_t)bh*131072 + (size_t)(d0+ty)*2048;
    dr[j0+tx]        = __bfloat16_as_ushort(hb);
    dr[1024 + j0+tx] = __bfloat16_as_ushort(lb);
}

__global__ void lut_prep(const int* __restrict__ rp)
{
    int r = threadIdx.x;
    int bp = rp[(size_t)r * S];
    int bn = rp[r];
    #define CLIP(v) ((v) < 0 ? 0 : ((v) > 511 ? 511 : (v)))
    g_lutC[1023 + r] = (short)CLIP(bp + 256);
    g_lutC[1023 - r] = (short)CLIP(bn + 256);
    g_lutP[1023 + r] = (short)CLIP(256 - bn);
    g_lutP[1023 - r] = (short)CLIP(256 - bp);
    #undef CLIP
}

// ---------------- attn_logits (R11-validated, unchanged) ----------------
#define AT_T0 0
#define AT_T1 34816
#define AT_Q  69632
#define AT_LC 73984
#define AT_LP 78080
#define AT_SMEM 82176
#define LGS_STRIDE 1028

__global__ void __launch_bounds__(256, 2) attn_logits(
    float* __restrict__ out_probs, float* __restrict__ out_logits)
{
    extern __shared__ char sm[];
    short* lutC = (short*)(sm + AT_LC);
    short* lutP = (short*)(sm + AT_LP);
    __shared__ float s_m[16][8];
    __shared__ float s_rowmax[16];
    __shared__ float s_red16[16][16];
    __shared__ float s_rinv[16];

    int it = blockIdx.x, bh = blockIdx.y;
    int i0 = it * 16;
    int t = threadIdx.x, wid = t >> 5, lid = t & 31;
    int wq = wid & 3, wbuf = wid >> 2;

    const __half* c2pB = g_c2pH + (size_t)bh * S * KPOS;
    const __half* p2cB = g_p2cH + (size_t)bh * S * KPOS;

    ((uint4*)(sm + AT_LC))[t] = ((const uint4*)g_lutC)[t];
    ((uint4*)(sm + AT_LP))[t] = ((const uint4*)g_lutP)[t];
    {
        int row = t >> 4, off = t & 15;
        *(uint4*)(sm + AT_Q + row*272 + off*16) =
            *(const uint4*)(g_Qsp + (((size_t)bh*1024 + i0 + row) << 7) + off*8);
    }

    {
        int row = t >> 1, part = t & 1;
        uint32_t dstb = smem_u32(sm) + AT_T0 + row*272 + part*128;
        const unsigned short* src = g_Ksp + (((size_t)bh*1024 + row) << 7) + part*64;
        #pragma unroll
        for (int q = 0; q < 8; q++) CP_ASYNC16(dstb + q*16, src + q*8);
        CP_COMMIT();
    }

    int rowA  = (lid & 7) + ((lid >> 3) & 1) * 8;
    int koffA = ((lid >> 4) & 1) * 16;
    int rowB  = (lid & 7) + ((lid >> 4) & 1) * 8;
    int koffB = ((lid >> 3) & 1) * 16;
    int r  = lid >> 2;
    int cc = 2 * (lid & 3);

    float lgr[8][2][4];
    float rmax2[2] = { -3.4e38f, -3.4e38f };
    uint32_t qbase = smem_u32(sm) + AT_Q;

    #pragma unroll
    for (int g = 0; g < 8; g++) {
        if (g < 7) {
            int row = t >> 1, part = t & 1;
            uint32_t dstb = smem_u32(sm) + ((g+1)&1 ? AT_T1 : AT_T0) + row*272 + part*128;
            const unsigned short* src = g_Ksp +
                (((size_t)bh*1024 + (g+1)*128 + row) << 7) + part*64;
            #pragma unroll
            for (int q = 0; q < 8; q++) CP_ASYNC16(dstb + q*16, src + q*8);
            CP_COMMIT();
            CP_WAIT1();
        } else {
            CP_WAIT0();
        }
        __syncthreads();

        uint32_t kbase = smem_u32(sm) + (g&1 ? AT_T1 : AT_T0) + wbuf*64*272;
        float c[2][4] = {{0,0,0,0},{0,0,0,0}};

        #pragma unroll
        for (int s = 0; s < 4; s++) {
            uint32_t ah[4], al[4], bhr[4], blr[4];
            uint32_t qa = qbase + rowA*272 + s*32 + koffA;
            LDMATRIX_X4(ah[0], ah[1], ah[2], ah[3], qa);
            LDMATRIX_X4(al[0], al[1], al[2], al[3], qa + 128);
            uint32_t ba = kbase + (wq*16 + rowB)*272 + s*32 + koffB;
            LDMATRIX_X4(bhr[0], bhr[1], bhr[2], bhr[3], ba);
            LDMATRIX_X4(blr[0], blr[1], blr[2], blr[3], ba + 128);
            #pragma unroll
            for (int nt = 0; nt < 2; nt++) {
                uint32_t bhf[2] = { bhr[nt*2], bhr[nt*2+1] };
                uint32_t blf[2] = { blr[nt*2], blr[nt*2+1] };
                MMA_BF16(c[nt], ah, bhf);
                MMA_BF16(c[nt], ah, blf);
                MMA_BF16(c[nt], al, bhf);
            }
        }

        int jt = 2*g + wbuf;
        #pragma unroll
        for (int nt = 0; nt < 2; nt++) {
            int jg = jt*64 + wq*16 + nt*8 + cc;
            #pragma unroll
            for (int e = 0; e < 4; e++) {
                int ig = i0 + r + (e >> 1) * 8;
                int j  = jg + (e & 1);
                int rel = ig - j + 1023;
                float l = c[nt][e] * SCALE
                        + __half2float(c2pB[((size_t)ig << 9) + lutC[rel]])
                        + __half2float(p2cB[((size_t)j  << 9) + lutP[rel]]);
                lgr[g][nt][e] = l;
                rmax2[e >> 1] = fmaxf(rmax2[e >> 1], l);
            }
        }
        __syncthreads();
    }

    #pragma unroll
    for (int e = 0; e < 2; e++) {
        float v = rmax2[e];
        v = fmaxf(v, __shfl_xor_sync(0xffffffff, v, 1));
        v = fmaxf(v, __shfl_xor_sync(0xffffffff, v, 2));
        if ((lid & 3) == 0) s_m[r + e*8][wid] = v;
    }
    __syncthreads();
    if (t < 16) {
        float m = s_m[t][0];
        #pragma unroll
        for (int x = 1; x < 8; x++) m = fmaxf(m, s_m[t][x]);
        s_rowmax[t] = m;
    }
    __syncthreads();

    float* lgs = (float*)sm;
    {
        float rmA = s_rowmax[r], rmB = s_rowmax[r + 8];
        #pragma unroll
        for (int g = 0; g < 8; g++) {
            int jt = 2*g + wbuf;
            #pragma unroll
            for (int nt = 0; nt < 2; nt++) {
                int jg = jt*64 + wq*16 + nt*8 + cc;
                *(float2*)&lgs[r*LGS_STRIDE + jg] =
                    make_float2(lgr[g][nt][0] - rmA, lgr[g][nt][1] - rmA);
                *(float2*)&lgs[(r+8)*LGS_STRIDE + jg] =
                    make_float2(lgr[g][nt][2] - rmB, lgr[g][nt][3] - rmB);
            }
        }
    }
    __syncthreads();

    int row = t >> 4, c0 = t & 15;
    float4* lrow  = (float4*)(lgs + row * LGS_STRIDE);
    float4* glrow = (float4*)(out_logits + ((size_t)bh * S + i0 + row) * S);
    float ssum = 0.f;
    #pragma unroll
    for (int c = 0; c < 16; c++) {
        int c4 = c0 + 16*c;
        float4 v = lrow[c4];
        glrow[c4] = v;
        float4 e;
        e.x = __expf(v.x); e.y = __expf(v.y);
        e.z = __expf(v.z); e.w = __expf(v.w);
        lrow[c4] = e;
        ssum += e.x + e.y + e.z + e.w;
    }
    s_red16[row][c0] = ssum;
    __syncthreads();
    if (t < 16) {
        float ssu = 0.f;
        #pragma unroll
        for (int x = 0; x < 16; x++) ssu += s_red16[t][x];
        s_rinv[t] = 1.0f / ssu;
    }
    __syncthreads();

    float inv = s_rinv[row];
    float4* gprow = (float4*)(out_probs + ((size_t)bh * S + i0 + row) * S);
    #pragma unroll
    for (int c = 0; c < 16; c++) {
        int c4 = c0 + 16*c;
        float4 e = lrow[c4];
        e.x *= inv; e.y *= inv; e.z *= inv; e.w *= inv;
        gprow[c4] = e;
    }
}

// ---------------- ctx_gemm (R10-validated, unchanged) ----------
#define CTX_AH 0
#define CTX_AL 10240
#define CTX_BH 20480
#define CTX_BL 25600
#define CTX_STAGE 30720
#define CTX_SMEM (2*CTX_STAGE)

__global__ void __launch_bounds__(256) ctx_gemm(
    const float* __restrict__ probs, float* __restrict__ out_ctx)
{
    extern __shared__ char sm[];
    int m0 = blockIdx.x * 128, bh = blockIdx.y;
    int b = bh >> 4, h = bh & 15;
    const float* A = probs + (size_t)bh * S * S;
    const unsigned short* B = g_Vtsp + ((size_t)bh << 17);

    int t = threadIdx.x, wid = t >> 5, lid = t & 31;
    int wm = wid & 3, wn = wid >> 2;

    int rowA  = (lid & 7) + ((lid >> 3) & 1) * 8;
    int koffA = ((lid >> 4) & 1) * 16;
    int rowB  = (lid & 7) + ((lid >> 4) & 1) * 8;
    int koffB = ((lid >> 3) & 1) * 16;

    float c[2][4][4];
    #pragma unroll
    for (int i = 0; i < 2; i++)
        #pragma unroll
        for (int j = 0; j < 4; j++)
            #pragma unroll
            for (int e = 0; e < 4; e++) c[i][j][e] = 0.f;

    float4 pa[4];
    uint4  pbv[2];
    int bslot0 = 2*t, bslot1 = 2*t + 1;

    #pragma unroll
    for (int q = 0; q < 4; q++) {
        int f = t + 256*q, row = f >> 3, c4 = f & 7;
        pa[q] = *(const float4*)(A + (size_t)(m0 + row) * S + c4*4);
    }
    {
        int s0 = bslot0, part = s0 >> 8, rr = (s0 & 255) >> 2, ch = s0 & 3;
        pbv[0] = *(const uint4*)(B + (size_t)rr*2048 + part*1024 + ch*8);
        int s1 = bslot1; part = s1 >> 8; rr = (s1 & 255) >> 2; ch = s1 & 3;
        pbv[1] = *(const uint4*)(B + (size_t)rr*2048 + part*1024 + ch*8);
    }
    {
        char* base = sm;
        #pragma unroll
        for (int q = 0; q < 4; q++) {
            int f = t + 256*q, row = f >> 3, c4 = f & 7;
            uint32_t off = (uint32_t)(row*80 + c4*8);
            uint2 hh, ll;
            split2(pa[q].x, pa[q].y, hh.x, ll.x);
            split2(pa[q].z, pa[q].w, hh.y, ll.y);
            *(uint2*)(base + CTX_AH + off) = hh;
            *(uint2*)(base + CTX_AL + off) = ll;
        }
        int s0 = bslot0, part = s0 >> 8, rr = (s0 & 255) >> 2, ch = s0 & 3;
        *(uint4*)(base + (part ? CTX_BL : CTX_BH) + rr*80 + ch*16) = pbv[0];
        int s1 = bslot1; part = s1 >> 8; rr = (s1 & 255) >> 2; ch = s1 & 3;
        *(uint4*)(base + (part ? CTX_BL : CTX_BH) + rr*80 + ch*16) = pbv[1];
    }
    __syncthreads();

    for (int kt = 0; kt < 32; kt++) {
        if (kt + 1 < 32) {
            #pragma unroll
            for (int q = 0; q < 4; q++) {
                int f = t + 256*q, row = f >> 3, c4 = f & 7;
                pa[q] = *(const float4*)(A + (size_t)(m0 + row) * S + (kt+1)*32 + c4*4);
            }
            int s0 = bslot0, part = s0 >> 8, rr = (s0 & 255) >> 2, ch = s0 & 3;
            pbv[0] = *(const uint4*)(B + (size_t)rr*2048 + part*1024 + (kt+1)*32 + ch*8);
            int s1 = bslot1; part = s1 >> 8; rr = (s1 & 255) >> 2; ch = s1 & 3;
            pbv[1] = *(const uint4*)(B + (size_t)rr*2048 + part*1024 + (kt+1)*32 + ch*8);
        }

        uint32_t base = smem_u32(sm) + (kt & 1) * CTX_STAGE;
        uint32_t aH = base + CTX_AH, aL = base + CTX_AL;
        uint32_t bH = base + CTX_BH, bL = base + CTX_BL;

        #pragma unroll
        for (int s = 0; s < 2; s++) {
            uint32_t ah[2][4], al[2][4], bh2[2][4], bl2[2][4];
            #pragma unroll
            for (int mt = 0; mt < 2; mt++) {
                uint32_t ro = (uint32_t)((wm*32 + mt*16 + rowA)*80 + s*32 + koffA);
                LDMATRIX_X4(ah[mt][0], ah[mt][1], ah[mt][2], ah[mt][3], aH + ro);
                LDMATRIX_X4(al[mt][0], al[mt][1], al[mt][2], al[mt][3], aL + ro);
            }
            #pragma unroll
            for (int q = 0; q < 2; q++) {
                uint32_t ro = (uint32_t)((wn*32 + q*16 + rowB)*80 + s*32 + koffB);
                LDMATRIX_X4(bh2[q][0], bh2[q][1], bh2[q][2], bh2[q][3], bH + ro);
                LDMATRIX_X4(bl2[q][0], bl2[q][1], bl2[q][2], bl2[q][3], bL + ro);
            }
            #pragma unroll
            for (int mt = 0; mt < 2; mt++) {
                #pragma unroll
                for (int nt = 0; nt < 4; nt++) {
                    uint32_t bhf[2] = { bh2[nt>>1][(nt&1)*2], bh2[nt>>1][(nt&1)*2+1] };
                    uint32_t blf[2] = { bl2[nt>>1][(nt&1)*2], bl2[nt>>1][(nt&1)*2+1] };
                    MMA_BF16(c[mt][nt], ah[mt], bhf);
                    MMA_BF16(c[mt][nt], ah[mt], blf);
                    MMA_BF16(c[mt][nt], al[mt], bhf);
                }
            }
        }

        if (kt + 1 < 32) {
            char* nb = sm + ((kt+1) & 1) * CTX_STAGE;
            #pragma unroll
            for (int q = 0; q < 4; q++) {
                int f = t + 256*q, row = f >> 3, c4 = f & 7;
                uint32_t off = (uint32_t)(row*80 + c4*8);
                uint2 hh, ll;
                split2(pa[q].x, pa[q].y, hh.x, ll.x);
                split2(pa[q].z, pa[q].w, hh.y, ll.y);
                *(uint2*)(nb + CTX_AH + off) = hh;
                *(uint2*)(nb + CTX_AL + off) = ll;
            }
            int s0 = bslot0, part = s0 >> 8, rr = (s0 & 255) >> 2, ch = s0 & 3;
            *(uint4*)(nb + (part ? CTX_BL : CTX_BH) + rr*80 + ch*16) = pbv[0];
            int s1 = bslot1; part = s1 >> 8; rr = (s1 & 255) >> 2; ch = s1 & 3;
            *(uint4*)(nb + (part ? CTX_BL : CTX_BH) + rr*80 + ch*16) = pbv[1];
        }
        __syncthreads();
    }

    #pragma unroll
    for (int mt = 0; mt < 2; mt++) {
        #pragma unroll
        for (int nt = 0; nt < 4; nt++) {
            int m = m0 + wm*32 + mt*16 + (lid >> 2);
            int n = wn*32 + nt*8 + 2*(lid & 3);
            float* drow = out_ctx + ((size_t)(b*1024 + m))*1024 + h*64 + n;
            *(float2*)drow = make_float2(c[mt][nt][0], c[mt][nt][1]);
            *(float2*)(drow + (size_t)8*1024) = make_float2(c[mt][nt][2], c[mt][nt][3]);
        }
    }
}

// ---------------- launch ----------------
extern "C" void kernel_launch(void* const* d_in, const int* in_sizes, int n_in,
                              void* d_out, int out_size)
{
    const float* hidden = (const float*)d_in[0];
    const int*   rp     = (const int*)  d_in[2];
    const float* rel    = (const float*)d_in[3];
    const float* Wq     = (const float*)d_in[4];
    const float* bq     = (const float*)d_in[5];
    const float* Wk     = (const float*)d_in[6];
    const float* bk     = (const float*)d_in[7];
    const float* Wv     = (const float*)d_in[8];
    const float* bv     = (const float*)d_in[9];

    float* out        = (float*)d_out;
    float* out_ctx    = out;
    float* out_probs  = out + (size_t)BB*S*HID;
    float* out_logits = out_probs + (size_t)BB*H*S*S;

    cudaFuncSetAttribute(gemm_bf16,
                         cudaFuncAttributeMaxDynamicSharedMemorySize, GB_SMEM);
    cudaFuncSetAttribute(attn_logits,
                         cudaFuncAttributeMaxDynamicSharedMemorySize, AT_SMEM);
    cudaFuncSetAttribute(ctx_gemm,
                         cudaFuncAttributeMaxDynamicSharedMemorySize, CTX_SMEM);

    unsigned short* d_hidsp; cudaGetSymbolAddress((void**)&d_hidsp, g_hidsp);
    unsigned short* d_relsp; cudaGetSymbolAddress((void**)&d_relsp, g_relsp);

    // launch index 3 (gemm mode0) is the one ncu captures
    split_wide<<<2048, 256>>>(hidden, d_hidsp);                  // 0
    split_w3<<<3072, 256>>>(Wq, Wk, Wv);                         // 1
    split_wide<<<512,  256>>>(rel,    d_relsp);                  // 2
    gemm_bf16<<<dim3(16, 8, 3), 256, GB_SMEM>>>(bq, bk, bv, 0);  // 3 <- profiled
    lut_prep<<<1, 1024>>>(rp);                                   // 4
    gemm_bf16<<<dim3(4,  8, 2), 256, GB_SMEM>>>(bq, bk, bv, 1);  // 5
    transpose_v<<<dim3(32, 2, 32), dim3(32, 32)>>>();            // 6
    gemm_bf16<<<dim3(8, 4, 64), 256, GB_SMEM>>>(bq, bk, bv, 2);  // 7
    attn_logits<<<dim3(64, 32), 256, AT_SMEM>>>(out_probs, out_logits); // 8
    ctx_gemm<<<dim3(8, 32), 256, CTX_SMEM>>>(out_probs, out_ctx);       // 9
}

// round 16
// speedup vs baseline: 1.1345x; 1.1345x over previous
#include <cuda_runtime.h>
#include <cuda_bf16.h>
#include <cuda_fp16.h>
#include <cstdint>

#define H   16
#define S   1024
#define D   64
#define HID 1024
#define BB  2
#define KPOS 512   /* 2K */
#define SCALE 0.07216878364870323f  /* 1/sqrt(64*3) */

// ---------------- scratch (static device memory; no allocation) ----------------
__device__ float g_V[BB*H*S*D];                 // fp32 V (transpose_v input)
__device__ unsigned short g_hidsp[BB*S*2048];   // bf16 split [row][1024 hi | 1024 lo]
__device__ unsigned short g_relsp[KPOS*2048];   // bf16 split
__device__ unsigned short g_Wsp[3*HID*2048];    // bf16 split Wq | Wk | Wv
__device__ __half g_Qp[BB*H*S*64];              // fp16 plain
__device__ __half g_Kp[BB*H*S*64];              // fp16 plain
__device__ unsigned short g_Ksp[BB*H*S*128];    // fp16 split [64 hi | 64 lo]
__device__ unsigned short g_posKsp[H*KPOS*128]; // fp16 split
__device__ unsigned short g_posQsp[H*KPOS*128]; // fp16 split
__device__ unsigned short g_Vtsp[BB*H*64*2048]; // fp16 split [bh][d][1024 hi | 1024 lo]
__device__ __half g_Pp[BB*H*S*1024];            // fp16 plain probs
__device__ __half g_c2pH[BB*H*S*KPOS];
__device__ __half g_p2cH[BB*H*S*KPOS];
__device__ short g_lutC[2048];
__device__ short g_lutP[2048];

__device__ __forceinline__ uint32_t smem_u32(const void* p) {
    uint32_t a;
    asm("{ .reg .u64 t; cvta.to.shared.u64 t, %1; cvt.u32.u64 %0, t; }" : "=r"(a) : "l"(p));
    return a;
}

#define CP_ASYNC16(dst, src) \
    asm volatile("cp.async.cg.shared.global [%0], [%1], 16;" :: "r"(dst), "l"(src))
#define CP_COMMIT()  asm volatile("cp.async.commit_group;" ::: "memory")
#define CP_WAIT0()   asm volatile("cp.async.wait_group 0;"  ::: "memory")
#define CP_WAIT1()   asm volatile("cp.async.wait_group 1;"  ::: "memory")

#define LDMATRIX_X4(r0, r1, r2, r3, addr) \
    asm volatile("ldmatrix.sync.aligned.m8n8.x4.shared.b16 {%0,%1,%2,%3}, [%4];" \
        : "=r"(r0), "=r"(r1), "=r"(r2), "=r"(r3) : "r"(addr))

#define MMA_BF16(c, a, b) \
    asm volatile("mma.sync.aligned.m16n8k16.row.col.f32.bf16.bf16.f32 " \
        "{%0,%1,%2,%3}, {%4,%5,%6,%7}, {%8,%9}, {%0,%1,%2,%3};" \
        : "+f"((c)[0]), "+f"((c)[1]), "+f"((c)[2]), "+f"((c)[3]) \
        : "r"((a)[0]), "r"((a)[1]), "r"((a)[2]), "r"((a)[3]), "r"((b)[0]), "r"((b)[1]))

#define MMA_FP16(c, a, b) \
    asm volatile("mma.sync.aligned.m16n8k16.row.col.f32.f16.f16.f32 " \
        "{%0,%1,%2,%3}, {%4,%5,%6,%7}, {%8,%9}, {%0,%1,%2,%3};" \
        : "+f"((c)[0]), "+f"((c)[1]), "+f"((c)[2]), "+f"((c)[3]) \
        : "r"((a)[0]), "r"((a)[1]), "r"((a)[2]), "r"((a)[3]), "r"((b)[0]), "r"((b)[1]))

__device__ __forceinline__ void split2(float x, float y, uint32_t& hi, uint32_t& lo) {
    __nv_bfloat16 hx = __float2bfloat16(x);
    __nv_bfloat16 hy = __float2bfloat16(y);
    __nv_bfloat16 lx = __float2bfloat16(x - __bfloat162float(hx));
    __nv_bfloat16 ly = __float2bfloat16(y - __bfloat162float(hy));
    hi = ((uint32_t)__bfloat16_as_ushort(hy) << 16) | __bfloat16_as_ushort(hx);
    lo = ((uint32_t)__bfloat16_as_ushort(ly) << 16) | __bfloat16_as_ushort(lx);
}

__device__ __forceinline__ void split2h(float x, float y, uint32_t& hi, uint32_t& lo) {
    __half hx = __float2half_rn(x);
    __half hy = __float2half_rn(y);
    __half lx = __float2half_rn(x - __half2float(hx));
    __half ly = __float2half_rn(y - __half2float(hy));
    hi = ((uint32_t)__half_as_ushort(hy) << 16) | __half_as_ushort(hx);
    lo = ((uint32_t)__half_as_ushort(ly) << 16) | __half_as_ushort(lx);
}

// ---------------- prep: bf16 split (unchanged) ----------------
__global__ void split_wide(const float* __restrict__ src, unsigned short* __restrict__ dst)
{
    int f4 = blockIdx.x * 256 + threadIdx.x;
    int row = f4 >> 8, c4 = (f4 & 255) * 4;
    float4 v = *(const float4*)(src + (size_t)f4 * 4);
    uint32_t h0, l0, h1, l1;
    split2(v.x, v.y, h0, l0);
    split2(v.z, v.w, h1, l1);
    unsigned short* r = dst + (size_t)row * 2048;
    *(uint2*)(r + c4)        = make_uint2(h0, h1);
    *(uint2*)(r + 1024 + c4) = make_uint2(l0, l1);
}

__global__ void split_w3(const float* __restrict__ Wq, const float* __restrict__ Wk,
                         const float* __restrict__ Wv)
{
    int row = blockIdx.x;
    int which = row >> 10, lr = row & 1023;
    const float* src = (which==0) ? Wq : ((which==1) ? Wk : Wv);
    int c4 = threadIdx.x * 4;
    float4 v = *(const float4*)(src + (size_t)lr * 1024 + c4);
    uint32_t h0, l0, h1, l1;
    split2(v.x, v.y, h0, l0);
    split2(v.z, v.w, h1, l1);
    unsigned short* r = g_Wsp + (size_t)row * 2048;
    *(uint2*)(r + c4)        = make_uint2(h0, h1);
    *(uint2*)(r + 1024 + c4) = make_uint2(l0, l1);
}

// ---------------- gemm_bf16: projections (3-term bf16, validated pipeline) -----
#define GB_STAGE 40960
#define GB_SMEM  (2*GB_STAGE)

__global__ void __launch_bounds__(256, 2) gemm_bf16(
    const float* __restrict__ bq, const float* __restrict__ bk,
    const float* __restrict__ bv, int mode)
{
    extern __shared__ char sm[];
    int z = blockIdx.z;
    const unsigned short *A, *B;
    const float* bias;
    if (mode == 0) {
        A = g_hidsp;
        B = g_Wsp + (size_t)z*HID*2048;
        bias = (z==0) ? bq : ((z==1) ? bk : bv);
    } else {
        A = g_relsp;
        B = g_Wsp + (size_t)(z ? 0 : 1)*HID*2048;
        bias = z ? bq : bk;
    }
    const int KT = 32;

    int m0 = blockIdx.x * 128, n0 = blockIdx.y * 128;
    int t = threadIdx.x, wid = t >> 5, lid = t & 31;
    int wm = wid & 1, wn = wid >> 1;

    float c[4][4][4];
    #pragma unroll
    for (int i = 0; i < 4; i++)
        #pragma unroll
        for (int j = 0; j < 4; j++)
            #pragma unroll
            for (int r = 0; r < 4; r++) c[i][j][r] = 0.f;

    int rowA  = (lid & 7) + ((lid >> 3) & 1) * 8;
    int koffA = ((lid >> 4) & 1) * 16;
    int rowB  = (lid & 7) + ((lid >> 4) & 1) * 8;
    int koffB = ((lid >> 3) & 1) * 16;

    #define G_ISSUE(stage, kt) do { \
        uint32_t sbase = smem_u32(sm) + (stage) * GB_STAGE; \
        _Pragma("unroll") \
        for (int q = 0; q < 4; q++) { \
            int idx = t + 256*q, row = idx >> 3, cch = idx & 7; \
            int part = cch >> 2, ch = cch & 3; \
            const unsigned short* srcA = A + (size_t)(m0+row)*2048 + part*1024 + (kt)*32 + ch*8; \
            CP_ASYNC16(sbase + part*10240 + row*80 + ch*16, srcA); \
            const unsigned short* srcB = B + (size_t)(n0+row)*2048 + part*1024 + (kt)*32 + ch*8; \
            CP_ASYNC16(sbase + 20480 + part*10240 + row*80 + ch*16, srcB); \
        } \
        CP_COMMIT(); \
    } while (0)

    G_ISSUE(0, 0);

    for (int kt = 0; kt < KT; kt++) {
        if (kt + 1 < KT) { G_ISSUE((kt + 1) & 1, kt + 1); CP_WAIT1(); }
        else             { CP_WAIT0(); }
        __syncthreads();

        uint32_t aH = smem_u32(sm) + (kt & 1) * GB_STAGE;
        uint32_t aL = aH + 10240, bH = aH + 20480, bL = aH + 30720;

        #pragma unroll
        for (int s = 0; s < 2; s++) {
            uint32_t ah[4][4], al[4][4], bh[2][4], bl[2][4];
            #pragma unroll
            for (int mt = 0; mt < 4; mt++) {
                uint32_t ro = (uint32_t)((wm*64 + mt*16 + rowA) * 80 + s*32 + koffA);
                LDMATRIX_X4(ah[mt][0], ah[mt][1], ah[mt][2], ah[mt][3], aH + ro);
                LDMATRIX_X4(al[mt][0], al[mt][1], al[mt][2], al[mt][3], aL + ro);
            }
            #pragma unroll
            for (int q = 0; q < 2; q++) {
                uint32_t ro = (uint32_t)((wn*32 + q*16 + rowB) * 80 + s*32 + koffB);
                LDMATRIX_X4(bh[q][0], bh[q][1], bh[q][2], bh[q][3], bH + ro);
                LDMATRIX_X4(bl[q][0], bl[q][1], bl[q][2], bl[q][3], bL + ro);
            }
            #pragma unroll
            for (int mt = 0; mt < 4; mt++) {
                #pragma unroll
                for (int nt = 0; nt < 4; nt++) {
                    uint32_t bhf[2] = { bh[nt>>1][(nt&1)*2], bh[nt>>1][(nt&1)*2+1] };
                    uint32_t blf[2] = { bl[nt>>1][(nt&1)*2], bl[nt>>1][(nt&1)*2+1] };
                    MMA_BF16(c[mt][nt], ah[mt], bhf);
                    MMA_BF16(c[mt][nt], ah[mt], blf);
                    MMA_BF16(c[mt][nt], al[mt], bhf);
                }
            }
        }
        if (kt + 2 < KT) __syncthreads();
    }

    // ---- epilogue: outputs in fp16 formats for the downstream 2-term kernels --
    #pragma unroll
    for (int mt = 0; mt < 4; mt++) {
        #pragma unroll
        for (int nt = 0; nt < 4; nt++) {
            int m = m0 + wm*64 + mt*16 + (lid >> 2);
            int n = n0 + wn*32 + nt*8  + 2*(lid & 3);
            float2 v0 = make_float2(c[mt][nt][0], c[mt][nt][1]);
            float2 v1 = make_float2(c[mt][nt][2], c[mt][nt][3]);
            float2 bb = *(const float2*)(bias + n);
            v0.x += bb.x; v0.y += bb.y; v1.x += bb.x; v1.y += bb.y;
            int hh = n >> 6, dd = n & 63;
            if (mode == 0 && z == 2) {
                int b = m >> 10, s2 = m & 1023;
                size_t bse = ((((size_t)b * H + hh) * S + s2) << 6) + dd;
                *(float2*)(g_V + bse) = v0;
                *(float2*)(g_V + bse + (8u << 6)) = v1;
            } else if (mode == 0) {
                int b = m >> 10, s2 = m & 1023;
                int bh2 = b * H + hh;
                size_t p0 = ((size_t)(bh2*1024 + s2))     << 6;
                size_t p1 = ((size_t)(bh2*1024 + s2 + 8)) << 6;
                if (z == 0) {
                    *(__half2*)(g_Qp + p0 + dd) = __floats2half2_rn(v0.x, v0.y);
                    *(__half2*)(g_Qp + p1 + dd) = __floats2half2_rn(v1.x, v1.y);
                } else {
                    *(__half2*)(g_Kp + p0 + dd) = __floats2half2_rn(v0.x, v0.y);
                    *(__half2*)(g_Kp + p1 + dd) = __floats2half2_rn(v1.x, v1.y);
                    uint32_t h0, l0;
                    split2h(v0.x, v0.y, h0, l0);
                    *(uint32_t*)(g_Ksp + 2*p0 + dd)      = h0;
                    *(uint32_t*)(g_Ksp + 2*p0 + 64 + dd) = l0;
                    split2h(v1.x, v1.y, h0, l0);
                    *(uint32_t*)(g_Ksp + 2*p1 + dd)      = h0;
                    *(uint32_t*)(g_Ksp + 2*p1 + 64 + dd) = l0;
                }
            } else {
                unsigned short* dstp = z ? g_posQsp : g_posKsp;
                size_t r0 = ((size_t)(hh*512 + m))     << 7;
                size_t r1 = ((size_t)(hh*512 + m + 8)) << 7;
                uint32_t h0, l0;
                split2h(v0.x, v0.y, h0, l0);
                *(uint32_t*)(dstp + r0 + dd)      = h0;
                *(uint32_t*)(dstp + r0 + 64 + dd) = l0;
                split2h(v1.x, v1.y, h0, l0);
                *(uint32_t*)(dstp + r1 + dd)      = h0;
                *(uint32_t*)(dstp + r1 + 64 + dd) = l0;
            }
        }
    }
    #undef G_ISSUE
}

// ---------------- cp_gemm: c2p/p2c via 2-term fp16, cp.async pipeline ----------
#define CG_STAGE 30720   /* A 10240 | BH 10240 | BL 10240 */
#define CG_SMEM  (2*CG_STAGE)

__global__ void __launch_bounds__(256, 2) cp_gemm()
{
    extern __shared__ char sm[];
    int z = blockIdx.z, sel = z >> 5, bh = z & 31, h = bh & 15;
    const __half* A = (sel ? g_Kp : g_Qp) + ((size_t)bh << 16);   // *1024*64
    const unsigned short* B = (sel ? g_posQsp : g_posKsp) + ((size_t)h << 16); // *512*128
    __half* dstH = (sel ? g_p2cH : g_c2pH) + (size_t)bh * S * KPOS;

    int m0 = blockIdx.x * 128, n0 = blockIdx.y * 128;
    int t = threadIdx.x, wid = t >> 5, lid = t & 31;
    int wm = wid & 1, wn = wid >> 1;

    float c[4][4][4];
    #pragma unroll
    for (int i = 0; i < 4; i++)
        #pragma unroll
        for (int j = 0; j < 4; j++)
            #pragma unroll
            for (int r = 0; r < 4; r++) c[i][j][r] = 0.f;

    int rowA  = (lid & 7) + ((lid >> 3) & 1) * 8;
    int koffA = ((lid >> 4) & 1) * 16;
    int rowB  = (lid & 7) + ((lid >> 4) & 1) * 8;
    int koffB = ((lid >> 3) & 1) * 16;

    #define CG_ISSUE(stage, kt) do { \
        uint32_t sbase = smem_u32(sm) + (stage) * CG_STAGE; \
        _Pragma("unroll") \
        for (int q = 0; q < 2; q++) { \
            int idx = t + 256*q, row = idx >> 2, ch = idx & 3; \
            const __half* srcA = A + (size_t)(m0+row)*64 + (kt)*32 + ch*8; \
            CP_ASYNC16(sbase + row*80 + ch*16, srcA); \
        } \
        _Pragma("unroll") \
        for (int q = 0; q < 4; q++) { \
            int idx = t + 256*q, part = idx >> 9, rem = idx & 511; \
            int row = rem >> 2, ch = rem & 3; \
            const unsigned short* srcB = B + (size_t)(n0+row)*128 + part*64 + (kt)*32 + ch*8; \
            CP_ASYNC16(sbase + 10240 + part*10240 + row*80 + ch*16, srcB); \
        } \
        CP_COMMIT(); \
    } while (0)

    CG_ISSUE(0, 0);

    for (int kt = 0; kt < 2; kt++) {
        if (kt == 0) { CG_ISSUE(1, 1); CP_WAIT1(); }
        else         { CP_WAIT0(); }
        __syncthreads();

        uint32_t aB = smem_u32(sm) + kt * CG_STAGE;
        uint32_t bH = aB + 10240, bL = aB + 20480;

        #pragma unroll
        for (int s = 0; s < 2; s++) {
            uint32_t a[4][4], bh4[2][4], bl4[2][4];
            #pragma unroll
            for (int mt = 0; mt < 4; mt++) {
                uint32_t ro = (uint32_t)((wm*64 + mt*16 + rowA) * 80 + s*32 + koffA);
                LDMATRIX_X4(a[mt][0], a[mt][1], a[mt][2], a[mt][3], aB + ro);
            }
            #pragma unroll
            for (int q = 0; q < 2; q++) {
                uint32_t ro = (uint32_t)((wn*32 + q*16 + rowB) * 80 + s*32 + koffB);
                LDMATRIX_X4(bh4[q][0], bh4[q][1], bh4[q][2], bh4[q][3], bH + ro);
                LDMATRIX_X4(bl4[q][0], bl4[q][1], bl4[q][2], bl4[q][3], bL + ro);
            }
            #pragma unroll
            for (int mt = 0; mt < 4; mt++) {
                #pragma unroll
                for (int nt = 0; nt < 4; nt++) {
                    uint32_t bhf[2] = { bh4[nt>>1][(nt&1)*2], bh4[nt>>1][(nt&1)*2+1] };
                    uint32_t blf[2] = { bl4[nt>>1][(nt&1)*2], bl4[nt>>1][(nt&1)*2+1] };
                    MMA_FP16(c[mt][nt], a[mt], bhf);
                    MMA_FP16(c[mt][nt], a[mt], blf);
                }
            }
        }
    }

    #pragma unroll
    for (int mt = 0; mt < 4; mt++) {
        #pragma unroll
        for (int nt = 0; nt < 4; nt++) {
            int m = m0 + wm*64 + mt*16 + (lid >> 2);
            int n = n0 + wn*32 + nt*8  + 2*(lid & 3);
            *(__half2*)(dstH + (size_t)m     * KPOS + n) =
                __floats2half2_rn(c[mt][nt][0]*SCALE, c[mt][nt][1]*SCALE);
            *(__half2*)(dstH + (size_t)(m+8) * KPOS + n) =
                __floats2half2_rn(c[mt][nt][2]*SCALE, c[mt][nt][3]*SCALE);
        }
    }
    #undef CG_ISSUE
}

// ---------------- transpose+split V (fp16) ----------------
__global__ void transpose_v()
{
    __shared__ float sm[32][33];
    int bh = blockIdx.z;
    int j0 = blockIdx.x * 32, d0 = blockIdx.y * 32;
    int tx = threadIdx.x, ty = threadIdx.y;
    sm[ty][tx] = g_V[(size_t)bh*65536 + (size_t)(j0+ty)*64 + d0+tx];
    __syncthreads();
    float val = sm[tx][ty];
    __half hb = __float2half_rn(val);
    __half lb = __float2half_rn(val - __half2float(hb));
    unsigned short* dr = g_Vtsp + (size_t)bh*131072 + (size_t)(d0+ty)*2048;
    dr[j0+tx]        = __half_as_ushort(hb);
    dr[1024 + j0+tx] = __half_as_ushort(lb);
}

__global__ void lut_prep(const int* __restrict__ rp)
{
    int r = threadIdx.x;
    int bp = rp[(size_t)r * S];
    int bn = rp[r];
    #define CLIP(v) ((v) < 0 ? 0 : ((v) > 511 ? 511 : (v)))
    g_lutC[1023 + r] = (short)CLIP(bp + 256);
    g_lutC[1023 - r] = (short)CLIP(bn + 256);
    g_lutP[1023 + r] = (short)CLIP(256 - bn);
    g_lutP[1023 - r] = (short)CLIP(256 - bp);
    #undef CLIP
}

// ---------------- attn_logits: fp16 2-term scores + gathers + softmax ----------
#define AT_T0 0                    /* 128 rows x 272B = 34816 */
#define AT_T1 34816
#define AT_Q  69632                /* Q plain fp16 16 x 144B = 2304 */
#define AT_LC 71936
#define AT_LP 76032
#define AT_SMEM 80128
#define LGS_STRIDE 1028

__global__ void __launch_bounds__(256, 2) attn_logits(
    float* __restrict__ out_probs, float* __restrict__ out_logits)
{
    extern __shared__ char sm[];
    short* lutC = (short*)(sm + AT_LC);
    short* lutP = (short*)(sm + AT_LP);
    __shared__ float s_m[16][8];
    __shared__ float s_rowmax[16];
    __shared__ float s_red16[16][16];
    __shared__ float s_rinv[16];

    int it = blockIdx.x, bh = blockIdx.y;
    int i0 = it * 16;
    int t = threadIdx.x, wid = t >> 5, lid = t & 31;
    int wq = wid & 3, wbuf = wid >> 2;

    const __half* c2pB = g_c2pH + (size_t)bh * S * KPOS;
    const __half* p2cB = g_p2cH + (size_t)bh * S * KPOS;

    ((uint4*)(sm + AT_LC))[t] = ((const uint4*)g_lutC)[t];
    ((uint4*)(sm + AT_LP))[t] = ((const uint4*)g_lutP)[t];
    if (t < 128) {
        int row = t >> 3, off = t & 7;
        *(uint4*)(sm + AT_Q + row*144 + off*16) =
            *(const uint4*)(g_Qp + (((size_t)bh*1024 + i0 + row) << 6) + off*8);
    }

    {
        int row = t >> 1, part = t & 1;
        uint32_t dstb = smem_u32(sm) + AT_T0 + row*272 + part*128;
        const unsigned short* src = g_Ksp + (((size_t)bh*1024 + row) << 7) + part*64;
        #pragma unroll
        for (int q = 0; q < 8; q++) CP_ASYNC16(dstb + q*16, src + q*8);
        CP_COMMIT();
    }

    int rowA  = (lid & 7) + ((lid >> 3) & 1) * 8;
    int koffA = ((lid >> 4) & 1) * 16;
    int rowB  = (lid & 7) + ((lid >> 4) & 1) * 8;
    int koffB = ((lid >> 3) & 1) * 16;
    int r  = lid >> 2;
    int cc = 2 * (lid & 3);

    float lgr[8][2][4];
    float rmax2[2] = { -3.4e38f, -3.4e38f };
    uint32_t qbase = smem_u32(sm) + AT_Q;

    #pragma unroll
    for (int g = 0; g < 8; g++) {
        if (g < 7) {
            int row = t >> 1, part = t & 1;
            uint32_t dstb = smem_u32(sm) + ((g+1)&1 ? AT_T1 : AT_T0) + row*272 + part*128;
            const unsigned short* src = g_Ksp +
                (((size_t)bh*1024 + (g+1)*128 + row) << 7) + part*64;
            #pragma unroll
            for (int q = 0; q < 8; q++) CP_ASYNC16(dstb + q*16, src + q*8);
            CP_COMMIT();
            CP_WAIT1();
        } else {
            CP_WAIT0();
        }
        __syncthreads();

        uint32_t kbase = smem_u32(sm) + (g&1 ? AT_T1 : AT_T0) + wbuf*64*272;
        float c[2][4] = {{0,0,0,0},{0,0,0,0}};

        #pragma unroll
        for (int s = 0; s < 4; s++) {
            uint32_t ah[4], bhr[4], blr[4];
            uint32_t qa = qbase + rowA*144 + s*32 + koffA;
            LDMATRIX_X4(ah[0], ah[1], ah[2], ah[3], qa);
            uint32_t ba = kbase + (wq*16 + rowB)*272 + s*32 + koffB;
            LDMATRIX_X4(bhr[0], bhr[1], bhr[2], bhr[3], ba);
            LDMATRIX_X4(blr[0], blr[1], blr[2], blr[3], ba + 128);
            #pragma unroll
            for (int nt = 0; nt < 2; nt++) {
                uint32_t bhf[2] = { bhr[nt*2], bhr[nt*2+1] };
                uint32_t blf[2] = { blr[nt*2], blr[nt*2+1] };
                MMA_FP16(c[nt], ah, bhf);
                MMA_FP16(c[nt], ah, blf);
            }
        }

        int jt = 2*g + wbuf;
        #pragma unroll
        for (int nt = 0; nt < 2; nt++) {
            int jg = jt*64 + wq*16 + nt*8 + cc;
            #pragma unroll
            for (int e = 0; e < 4; e++) {
                int ig = i0 + r + (e >> 1) * 8;
                int j  = jg + (e & 1);
                int rel = ig - j + 1023;
                float l = c[nt][e] * SCALE
                        + __half2float(c2pB[((size_t)ig << 9) + lutC[rel]])
                        + __half2float(p2cB[((size_t)j  << 9) + lutP[rel]]);
                lgr[g][nt][e] = l;
                rmax2[e >> 1] = fmaxf(rmax2[e >> 1], l);
            }
        }
        __syncthreads();
    }

    #pragma unroll
    for (int e = 0; e < 2; e++) {
        float v = rmax2[e];
        v = fmaxf(v, __shfl_xor_sync(0xffffffff, v, 1));
        v = fmaxf(v, __shfl_xor_sync(0xffffffff, v, 2));
        if ((lid & 3) == 0) s_m[r + e*8][wid] = v;
    }
    __syncthreads();
    if (t < 16) {
        float m = s_m[t][0];
        #pragma unroll
        for (int x = 1; x < 8; x++) m = fmaxf(m, s_m[t][x]);
        s_rowmax[t] = m;
    }
    __syncthreads();

    float* lgs = (float*)sm;
    {
        float rmA = s_rowmax[r], rmB = s_rowmax[r + 8];
        #pragma unroll
        for (int g = 0; g < 8; g++) {
            int jt = 2*g + wbuf;
            #pragma unroll
            for (int nt = 0; nt < 2; nt++) {
                int jg = jt*64 + wq*16 + nt*8 + cc;
                *(float2*)&lgs[r*LGS_STRIDE + jg] =
                    make_float2(lgr[g][nt][0] - rmA, lgr[g][nt][1] - rmA);
                *(float2*)&lgs[(r+8)*LGS_STRIDE + jg] =
                    make_float2(lgr[g][nt][2] - rmB, lgr[g][nt][3] - rmB);
            }
        }
    }
    __syncthreads();

    int row = t >> 4, c0 = t & 15;
    float4* lrow  = (float4*)(lgs + row * LGS_STRIDE);
    float4* glrow = (float4*)(out_logits + ((size_t)bh * S + i0 + row) * S);
    float ssum = 0.f;
    #pragma unroll
    for (int c = 0; c < 16; c++) {
        int c4 = c0 + 16*c;
        float4 v = lrow[c4];
        glrow[c4] = v;
        float4 e;
        e.x = __expf(v.x); e.y = __expf(v.y);
        e.z = __expf(v.z); e.w = __expf(v.w);
        lrow[c4] = e;
        ssum += e.x + e.y + e.z + e.w;
    }
    s_red16[row][c0] = ssum;
    __syncthreads();
    if (t < 16) {
        float ssu = 0.f;
        #pragma unroll
        for (int x = 0; x < 16; x++) ssu += s_red16[t][x];
        s_rinv[t] = 1.0f / ssu;
    }
    __syncthreads();

    float inv = s_rinv[row];
    float4* gprow = (float4*)(out_probs + ((size_t)bh * S + i0 + row) * S);
    __half* prow = g_Pp + (((size_t)bh*1024 + i0 + row) << 10);
    #pragma unroll
    for (int c = 0; c < 16; c++) {
        int c4 = c0 + 16*c;
        float4 e = lrow[c4];
        e.x *= inv; e.y *= inv; e.z *= inv; e.w *= inv;
        gprow[c4] = e;
        __half2 p0 = __floats2half2_rn(e.x, e.y);
        __half2 p1 = __floats2half2_rn(e.z, e.w);
        *(uint2*)(prow + 4*c4) = make_uint2(
            ((uint32_t)__half_as_ushort(p0.y) << 16) | __half_as_ushort(p0.x),
            ((uint32_t)__half_as_ushort(p1.y) << 16) | __half_as_ushort(p1.x));
    }
}

// ---------------- ctx_gemm: 2-term fp16, cp.async pipeline ----------
#define CX_STAGE 20480   /* A 10240 | BH 5120 | BL 5120 */
#define CX_SMEM (2*CX_STAGE)

__global__ void __launch_bounds__(256) ctx_gemm(float* __restrict__ out_ctx)
{
    extern __shared__ char sm[];
    int m0 = blockIdx.x * 128, bh = blockIdx.y;
    int b = bh >> 4, h = bh & 15;
    const __half* A = g_Pp + ((size_t)bh << 20);            // *1024*1024
    const unsigned short* B = g_Vtsp + ((size_t)bh << 17);  // *64*2048

    int t = threadIdx.x, wid = t >> 5, lid = t & 31;
    int wm = wid & 3, wn = wid >> 2;

    int rowA  = (lid & 7) + ((lid >> 3) & 1) * 8;
    int koffA = ((lid >> 4) & 1) * 16;
    int rowB  = (lid & 7) + ((lid >> 4) & 1) * 8;
    int koffB = ((lid >> 3) & 1) * 16;

    float c[2][4][4];
    #pragma unroll
    for (int i = 0; i < 2; i++)
        #pragma unroll
        for (int j = 0; j < 4; j++)
            #pragma unroll
            for (int e = 0; e < 4; e++) c[i][j][e] = 0.f;

    #define CX_ISSUE(stage, kt) do { \
        uint32_t sbase = smem_u32(sm) + (stage) * CX_STAGE; \
        _Pragma("unroll") \
        for (int q = 0; q < 2; q++) { \
            int idx = t + 256*q, row = idx >> 2, ch = idx & 3; \
            const __half* srcA = A + (size_t)(m0+row)*1024 + (kt)*32 + ch*8; \
            CP_ASYNC16(sbase + row*80 + ch*16, srcA); \
        } \
        _Pragma("unroll") \
        for (int q = 0; q < 2; q++) { \
            int idx = t + 256*q, part = idx >> 8, rem = idx & 255; \
            int row = rem >> 2, ch = rem & 3; \
            const unsigned short* srcB = B + (size_t)row*2048 + part*1024 + (kt)*32 + ch*8; \
            CP_ASYNC16(sbase + 10240 + part*5120 + row*80 + ch*16, srcB); \
        } \
        CP_COMMIT(); \
    } while (0)

    CX_ISSUE(0, 0);

    for (int kt = 0; kt < 32; kt++) {
        if (kt + 1 < 32) { CX_ISSUE((kt + 1) & 1, kt + 1); CP_WAIT1(); }
        else             { CP_WAIT0(); }
        __syncthreads();

        uint32_t aB = smem_u32(sm) + (kt & 1) * CX_STAGE;
        uint32_t bH = aB + 10240, bL = aB + 15360;

        #pragma unroll
        for (int s = 0; s < 2; s++) {
            uint32_t a[2][4], bh4[2][4], bl4[2][4];
            #pragma unroll
            for (int mt = 0; mt < 2; mt++) {
                uint32_t ro = (uint32_t)((wm*32 + mt*16 + rowA)*80 + s*32 + koffA);
                LDMATRIX_X4(a[mt][0], a[mt][1], a[mt][2], a[mt][3], aB + ro);
            }
            #pragma unroll
            for (int q = 0; q < 2; q++) {
                uint32_t ro = (uint32_t)((wn*32 + q*16 + rowB)*80 + s*32 + koffB);
                LDMATRIX_X4(bh4[q][0], bh4[q][1], bh4[q][2], bh4[q][3], bH + ro);
                LDMATRIX_X4(bl4[q][0], bl4[q][1], bl4[q][2], bl4[q][3], bL + ro);
            }
            #pragma unroll
            for (int mt = 0; mt < 2; mt++) {
                #pragma unroll
                for (int nt = 0; nt < 4; nt++) {
                    uint32_t bhf[2] = { bh4[nt>>1][(nt&1)*2], bh4[nt>>1][(nt&1)*2+1] };
                    uint32_t blf[2] = { bl4[nt>>1][(nt&1)*2], bl4[nt>>1][(nt&1)*2+1] };
                    MMA_FP16(c[mt][nt], a[mt], bhf);
                    MMA_FP16(c[mt][nt], a[mt], blf);
                }
            }
        }
        if (kt + 2 < 32) __syncthreads();
    }

    #pragma unroll
    for (int mt = 0; mt < 2; mt++) {
        #pragma unroll
        for (int nt = 0; nt < 4; nt++) {
            int m = m0 + wm*32 + mt*16 + (lid >> 2);
            int n = wn*32 + nt*8 + 2*(lid & 3);
            float* drow = out_ctx + ((size_t)(b*1024 + m))*1024 + h*64 + n;
            *(float2*)drow = make_float2(c[mt][nt][0], c[mt][nt][1]);
            *(float2*)(drow + (size_t)8*1024) = make_float2(c[mt][nt][2], c[mt][nt][3]);
        }
    }
    #undef CX_ISSUE
}

// ---------------- launch ----------------
extern "C" void kernel_launch(void* const* d_in, const int* in_sizes, int n_in,
                              void* d_out, int out_size)
{
    const float* hidden = (const float*)d_in[0];
    const int*   rp     = (const int*)  d_in[2];
    const float* rel    = (const float*)d_in[3];
    const float* Wq     = (const float*)d_in[4];
    const float* bq     = (const float*)d_in[5];
    const float* Wk     = (const float*)d_in[6];
    const float* bk     = (const float*)d_in[7];
    const float* Wv     = (const float*)d_in[8];
    const float* bv     = (const float*)d_in[9];

    float* out        = (float*)d_out;
    float* out_ctx    = out;
    float* out_probs  = out + (size_t)BB*S*HID;
    float* out_logits = out_probs + (size_t)BB*H*S*S;

    cudaFuncSetAttribute(gemm_bf16,
                         cudaFuncAttributeMaxDynamicSharedMemorySize, GB_SMEM);
    cudaFuncSetAttribute(cp_gemm,
                         cudaFuncAttributeMaxDynamicSharedMemorySize, CG_SMEM);
    cudaFuncSetAttribute(attn_logits,
                         cudaFuncAttributeMaxDynamicSharedMemorySize, AT_SMEM);
    cudaFuncSetAttribute(ctx_gemm,
                         cudaFuncAttributeMaxDynamicSharedMemorySize, CX_SMEM);

    unsigned short* d_hidsp; cudaGetSymbolAddress((void**)&d_hidsp, g_hidsp);
    unsigned short* d_relsp; cudaGetSymbolAddress((void**)&d_relsp, g_relsp);

    // launch index 3 (gemm mode0) is the one ncu captures
    split_wide<<<2048, 256>>>(hidden, d_hidsp);                  // 0
    split_w3<<<3072, 256>>>(Wq, Wk, Wv);                         // 1
    split_wide<<<512,  256>>>(rel,    d_relsp);                  // 2
    gemm_bf16<<<dim3(16, 8, 3), 256, GB_SMEM>>>(bq, bk, bv, 0);  // 3 <- profiled
    lut_prep<<<1, 1024>>>(rp);                                   // 4
    gemm_bf16<<<dim3(4,  8, 2), 256, GB_SMEM>>>(bq, bk, bv, 1);  // 5
    transpose_v<<<dim3(32, 2, 32), dim3(32, 32)>>>();            // 6
    cp_gemm<<<dim3(8, 4, 64), 256, CG_SMEM>>>();                 // 7
    attn_logits<<<dim3(64, 32), 256, AT_SMEM>>>(out_probs, out_logits); // 8
    ctx_gemm<<<dim3(8, 32), 256, CX_SMEM>>>(out_ctx);                   // 9
}

// round 17
// speedup vs baseline: 1.2266x; 1.0812x over previous
#include <cuda_runtime.h>
#include <cuda_bf16.h>
#include <cuda_fp16.h>
#include <cstdint>

#define H   16
#define S   1024
#define D   64
#define HID 1024
#define BB  2
#define KPOS 512   /* 2K */
#define SCALE 0.07216878364870323f  /* 1/sqrt(64*3) */

// ---------------- scratch (static device memory; no allocation) ----------------
__device__ float g_V[BB*H*S*D];                 // fp32 V (transpose_v input)
__device__ __half g_hidh[BB*S*HID];             // fp16 plain hidden
__device__ __half g_relh[KPOS*HID];             // fp16 plain rel_embeddings
__device__ unsigned short g_Wsp[3*HID*2048];    // fp16 split Wq | Wk | Wv
__device__ __half g_Qp[BB*H*S*64];              // fp16 plain
__device__ __half g_Kp[BB*H*S*64];              // fp16 plain
__device__ unsigned short g_Ksp[BB*H*S*128];    // fp16 split [64 hi | 64 lo]
__device__ unsigned short g_posKsp[H*KPOS*128]; // fp16 split
__device__ unsigned short g_posQsp[H*KPOS*128]; // fp16 split
__device__ unsigned short g_Vtsp[BB*H*64*2048]; // fp16 split [bh][d][1024 hi | 1024 lo]
__device__ __half g_Pp[BB*H*S*1024];            // fp16 plain probs
__device__ __half g_c2pH[BB*H*S*KPOS];
__device__ __half g_p2cH[BB*H*S*KPOS];
__device__ short g_lutC[2048];
__device__ short g_lutP[2048];

__device__ __forceinline__ uint32_t smem_u32(const void* p) {
    uint32_t a;
    asm("{ .reg .u64 t; cvta.to.shared.u64 t, %1; cvt.u32.u64 %0, t; }" : "=r"(a) : "l"(p));
    return a;
}

#define CP_ASYNC16(dst, src) \
    asm volatile("cp.async.cg.shared.global [%0], [%1], 16;" :: "r"(dst), "l"(src))
#define CP_COMMIT()  asm volatile("cp.async.commit_group;" ::: "memory")
#define CP_WAIT0()   asm volatile("cp.async.wait_group 0;"  ::: "memory")
#define CP_WAIT1()   asm volatile("cp.async.wait_group 1;"  ::: "memory")

#define LDMATRIX_X4(r0, r1, r2, r3, addr) \
    asm volatile("ldmatrix.sync.aligned.m8n8.x4.shared.b16 {%0,%1,%2,%3}, [%4];" \
        : "=r"(r0), "=r"(r1), "=r"(r2), "=r"(r3) : "r"(addr))

#define MMA_FP16(c, a, b) \
    asm volatile("mma.sync.aligned.m16n8k16.row.col.f32.f16.f16.f32 " \
        "{%0,%1,%2,%3}, {%4,%5,%6,%7}, {%8,%9}, {%0,%1,%2,%3};" \
        : "+f"((c)[0]), "+f"((c)[1]), "+f"((c)[2]), "+f"((c)[3]) \
        : "r"((a)[0]), "r"((a)[1]), "r"((a)[2]), "r"((a)[3]), "r"((b)[0]), "r"((b)[1]))

__device__ __forceinline__ void split2h(float x, float y, uint32_t& hi, uint32_t& lo) {
    __half hx = __float2half_rn(x);
    __half hy = __float2half_rn(y);
    __half lx = __float2half_rn(x - __half2float(hx));
    __half ly = __float2half_rn(y - __half2float(hy));
    hi = ((uint32_t)__half_as_ushort(hy) << 16) | __half_as_ushort(hx);
    lo = ((uint32_t)__half_as_ushort(ly) << 16) | __half_as_ushort(lx);
}

// ---------------- preps ----------------
__global__ void tofp16_wide(const float* __restrict__ src, __half* __restrict__ dst)
{
    int f4 = blockIdx.x * 256 + threadIdx.x;
    float4 v = *(const float4*)(src + (size_t)f4 * 4);
    __half2 a = __floats2half2_rn(v.x, v.y);
    __half2 b = __floats2half2_rn(v.z, v.w);
    *(uint2*)(dst + (size_t)f4 * 4) = make_uint2(
        ((uint32_t)__half_as_ushort(a.y) << 16) | __half_as_ushort(a.x),
        ((uint32_t)__half_as_ushort(b.y) << 16) | __half_as_ushort(b.x));
}

__global__ void split_w3(const float* __restrict__ Wq, const float* __restrict__ Wk,
                         const float* __restrict__ Wv)
{
    int row = blockIdx.x;
    int which = row >> 10, lr = row & 1023;
    const float* src = (which==0) ? Wq : ((which==1) ? Wk : Wv);
    int c4 = threadIdx.x * 4;
    float4 v = *(const float4*)(src + (size_t)lr * 1024 + c4);
    uint32_t h0, l0, h1, l1;
    split2h(v.x, v.y, h0, l0);
    split2h(v.z, v.w, h1, l1);
    unsigned short* r = g_Wsp + (size_t)row * 2048;
    *(uint2*)(r + c4)        = make_uint2(h0, h1);
    *(uint2*)(r + 1024 + c4) = make_uint2(l0, l1);
}

// ---------------- gemm_fp16: projections, A plain fp16 x B split, 2-MMA --------
#define GF_STAGE 30720   /* A 10240 | BH 10240 | BL 10240 */
#define GF_SMEM  (2*GF_STAGE)

__global__ void __launch_bounds__(256, 2) gemm_fp16(
    const float* __restrict__ bq, const float* __restrict__ bk,
    const float* __restrict__ bv, int mode)
{
    extern __shared__ char sm[];
    int z = blockIdx.z;
    const __half* A;
    const unsigned short* B;
    const float* bias;
    if (mode == 0) {
        A = g_hidh;
        B = g_Wsp + (size_t)z*HID*2048;
        bias = (z==0) ? bq : ((z==1) ? bk : bv);
    } else {
        A = g_relh;
        B = g_Wsp + (size_t)(z ? 0 : 1)*HID*2048;
        bias = z ? bq : bk;
    }
    const int KT = 32;

    int m0 = blockIdx.x * 128, n0 = blockIdx.y * 128;
    int t = threadIdx.x, wid = t >> 5, lid = t & 31;
    int wm = wid & 1, wn = wid >> 1;

    float c[4][4][4];
    #pragma unroll
    for (int i = 0; i < 4; i++)
        #pragma unroll
        for (int j = 0; j < 4; j++)
            #pragma unroll
            for (int r = 0; r < 4; r++) c[i][j][r] = 0.f;

    int rowA  = (lid & 7) + ((lid >> 3) & 1) * 8;
    int koffA = ((lid >> 4) & 1) * 16;
    int rowB  = (lid & 7) + ((lid >> 4) & 1) * 8;
    int koffB = ((lid >> 3) & 1) * 16;

    #define GF_ISSUE(stage, kt) do { \
        uint32_t sbase = smem_u32(sm) + (stage) * GF_STAGE; \
        _Pragma("unroll") \
        for (int q = 0; q < 2; q++) { \
            int idx = t + 256*q, row = idx >> 2, ch = idx & 3; \
            const __half* srcA = A + (size_t)(m0+row)*1024 + (kt)*32 + ch*8; \
            CP_ASYNC16(sbase + row*80 + ch*16, srcA); \
        } \
        _Pragma("unroll") \
        for (int q = 0; q < 4; q++) { \
            int idx = t + 256*q, part = idx >> 9, rem = idx & 511; \
            int row = rem >> 2, ch = rem & 3; \
            const unsigned short* srcB = B + (size_t)(n0+row)*2048 + part*1024 + (kt)*32 + ch*8; \
            CP_ASYNC16(sbase + 10240 + part*10240 + row*80 + ch*16, srcB); \
        } \
        CP_COMMIT(); \
    } while (0)

    GF_ISSUE(0, 0);

    for (int kt = 0; kt < KT; kt++) {
        if (kt + 1 < KT) { GF_ISSUE((kt + 1) & 1, kt + 1); CP_WAIT1(); }
        else             { CP_WAIT0(); }
        __syncthreads();

        uint32_t aB = smem_u32(sm) + (kt & 1) * GF_STAGE;
        uint32_t bH = aB + 10240, bL = aB + 20480;

        #pragma unroll
        for (int s = 0; s < 2; s++) {
            uint32_t a[4][4], bh4[2][4], bl4[2][4];
            #pragma unroll
            for (int mt = 0; mt < 4; mt++) {
                uint32_t ro = (uint32_t)((wm*64 + mt*16 + rowA) * 80 + s*32 + koffA);
                LDMATRIX_X4(a[mt][0], a[mt][1], a[mt][2], a[mt][3], aB + ro);
            }
            #pragma unroll
            for (int q = 0; q < 2; q++) {
                uint32_t ro = (uint32_t)((wn*32 + q*16 + rowB) * 80 + s*32 + koffB);
                LDMATRIX_X4(bh4[q][0], bh4[q][1], bh4[q][2], bh4[q][3], bH + ro);
                LDMATRIX_X4(bl4[q][0], bl4[q][1], bl4[q][2], bl4[q][3], bL + ro);
            }
            #pragma unroll
            for (int mt = 0; mt < 4; mt++) {
                #pragma unroll
                for (int nt = 0; nt < 4; nt++) {
                    uint32_t bhf[2] = { bh4[nt>>1][(nt&1)*2], bh4[nt>>1][(nt&1)*2+1] };
                    uint32_t blf[2] = { bl4[nt>>1][(nt&1)*2], bl4[nt>>1][(nt&1)*2+1] };
                    MMA_FP16(c[mt][nt], a[mt], bhf);
                    MMA_FP16(c[mt][nt], a[mt], blf);
                }
            }
        }
        if (kt + 2 < KT) __syncthreads();
    }

    // ---- epilogue (identical output formats to R16) ----
    #pragma unroll
    for (int mt = 0; mt < 4; mt++) {
        #pragma unroll
        for (int nt = 0; nt < 4; nt++) {
            int m = m0 + wm*64 + mt*16 + (lid >> 2);
            int n = n0 + wn*32 + nt*8  + 2*(lid & 3);
            float2 v0 = make_float2(c[mt][nt][0], c[mt][nt][1]);
            float2 v1 = make_float2(c[mt][nt][2], c[mt][nt][3]);
            float2 bb = *(const float2*)(bias + n);
            v0.x += bb.x; v0.y += bb.y; v1.x += bb.x; v1.y += bb.y;
            int hh = n >> 6, dd = n & 63;
            if (mode == 0 && z == 2) {
                int b = m >> 10, s2 = m & 1023;
                size_t bse = ((((size_t)b * H + hh) * S + s2) << 6) + dd;
                *(float2*)(g_V + bse) = v0;
                *(float2*)(g_V + bse + (8u << 6)) = v1;
            } else if (mode == 0) {
                int b = m >> 10, s2 = m & 1023;
                int bh2 = b * H + hh;
                size_t p0 = ((size_t)(bh2*1024 + s2))     << 6;
                size_t p1 = ((size_t)(bh2*1024 + s2 + 8)) << 6;
                if (z == 0) {
                    *(__half2*)(g_Qp + p0 + dd) = __floats2half2_rn(v0.x, v0.y);
                    *(__half2*)(g_Qp + p1 + dd) = __floats2half2_rn(v1.x, v1.y);
                } else {
                    *(__half2*)(g_Kp + p0 + dd) = __floats2half2_rn(v0.x, v0.y);
                    *(__half2*)(g_Kp + p1 + dd) = __floats2half2_rn(v1.x, v1.y);
                    uint32_t h0, l0;
                    split2h(v0.x, v0.y, h0, l0);
                    *(uint32_t*)(g_Ksp + 2*p0 + dd)      = h0;
                    *(uint32_t*)(g_Ksp + 2*p0 + 64 + dd) = l0;
                    split2h(v1.x, v1.y, h0, l0);
                    *(uint32_t*)(g_Ksp + 2*p1 + dd)      = h0;
                    *(uint32_t*)(g_Ksp + 2*p1 + 64 + dd) = l0;
                }
            } else {
                unsigned short* dstp = z ? g_posQsp : g_posKsp;
                size_t r0 = ((size_t)(hh*512 + m))     << 7;
                size_t r1 = ((size_t)(hh*512 + m + 8)) << 7;
                uint32_t h0, l0;
                split2h(v0.x, v0.y, h0, l0);
                *(uint32_t*)(dstp + r0 + dd)      = h0;
                *(uint32_t*)(dstp + r0 + 64 + dd) = l0;
                split2h(v1.x, v1.y, h0, l0);
                *(uint32_t*)(dstp + r1 + dd)      = h0;
                *(uint32_t*)(dstp + r1 + 64 + dd) = l0;
            }
        }
    }
    #undef GF_ISSUE
}

// ---------------- cp_gemm: c2p/p2c via 2-term fp16 (R16-validated) ----------
#define CG_STAGE 30720
#define CG_SMEM  (2*CG_STAGE)

__global__ void __launch_bounds__(256, 2) cp_gemm()
{
    extern __shared__ char sm[];
    int z = blockIdx.z, sel = z >> 5, bh = z & 31, h = bh & 15;
    const __half* A = (sel ? g_Kp : g_Qp) + ((size_t)bh << 16);
    const unsigned short* B = (sel ? g_posQsp : g_posKsp) + ((size_t)h << 16);
    __half* dstH = (sel ? g_p2cH : g_c2pH) + (size_t)bh * S * KPOS;

    int m0 = blockIdx.x * 128, n0 = blockIdx.y * 128;
    int t = threadIdx.x, wid = t >> 5, lid = t & 31;
    int wm = wid & 1, wn = wid >> 1;

    float c[4][4][4];
    #pragma unroll
    for (int i = 0; i < 4; i++)
        #pragma unroll
        for (int j = 0; j < 4; j++)
            #pragma unroll
            for (int r = 0; r < 4; r++) c[i][j][r] = 0.f;

    int rowA  = (lid & 7) + ((lid >> 3) & 1) * 8;
    int koffA = ((lid >> 4) & 1) * 16;
    int rowB  = (lid & 7) + ((lid >> 4) & 1) * 8;
    int koffB = ((lid >> 3) & 1) * 16;

    #define CG_ISSUE(stage, kt) do { \
        uint32_t sbase = smem_u32(sm) + (stage) * CG_STAGE; \
        _Pragma("unroll") \
        for (int q = 0; q < 2; q++) { \
            int idx = t + 256*q, row = idx >> 2, ch = idx & 3; \
            const __half* srcA = A + (size_t)(m0+row)*64 + (kt)*32 + ch*8; \
            CP_ASYNC16(sbase + row*80 + ch*16, srcA); \
        } \
        _Pragma("unroll") \
        for (int q = 0; q < 4; q++) { \
            int idx = t + 256*q, part = idx >> 9, rem = idx & 511; \
            int row = rem >> 2, ch = rem & 3; \
            const unsigned short* srcB = B + (size_t)(n0+row)*128 + part*64 + (kt)*32 + ch*8; \
            CP_ASYNC16(sbase + 10240 + part*10240 + row*80 + ch*16, srcB); \
        } \
        CP_COMMIT(); \
    } while (0)

    CG_ISSUE(0, 0);

    for (int kt = 0; kt < 2; kt++) {
        if (kt == 0) { CG_ISSUE(1, 1); CP_WAIT1(); }
        else         { CP_WAIT0(); }
        __syncthreads();

        uint32_t aB = smem_u32(sm) + kt * CG_STAGE;
        uint32_t bH = aB + 10240, bL = aB + 20480;

        #pragma unroll
        for (int s = 0; s < 2; s++) {
            uint32_t a[4][4], bh4[2][4], bl4[2][4];
            #pragma unroll
            for (int mt = 0; mt < 4; mt++) {
                uint32_t ro = (uint32_t)((wm*64 + mt*16 + rowA) * 80 + s*32 + koffA);
                LDMATRIX_X4(a[mt][0], a[mt][1], a[mt][2], a[mt][3], aB + ro);
            }
            #pragma unroll
            for (int q = 0; q < 2; q++) {
                uint32_t ro = (uint32_t)((wn*32 + q*16 + rowB) * 80 + s*32 + koffB);
                LDMATRIX_X4(bh4[q][0], bh4[q][1], bh4[q][2], bh4[q][3], bH + ro);
                LDMATRIX_X4(bl4[q][0], bl4[q][1], bl4[q][2], bl4[q][3], bL + ro);
            }
            #pragma unroll
            for (int mt = 0; mt < 4; mt++) {
                #pragma unroll
                for (int nt = 0; nt < 4; nt++) {
                    uint32_t bhf[2] = { bh4[nt>>1][(nt&1)*2], bh4[nt>>1][(nt&1)*2+1] };
                    uint32_t blf[2] = { bl4[nt>>1][(nt&1)*2], bl4[nt>>1][(nt&1)*2+1] };
                    MMA_FP16(c[mt][nt], a[mt], bhf);
                    MMA_FP16(c[mt][nt], a[mt], blf);
                }
            }
        }
    }

    #pragma unroll
    for (int mt = 0; mt < 4; mt++) {
        #pragma unroll
        for (int nt = 0; nt < 4; nt++) {
            int m = m0 + wm*64 + mt*16 + (lid >> 2);
            int n = n0 + wn*32 + nt*8  + 2*(lid & 3);
            *(__half2*)(dstH + (size_t)m     * KPOS + n) =
                __floats2half2_rn(c[mt][nt][0]*SCALE, c[mt][nt][1]*SCALE);
            *(__half2*)(dstH + (size_t)(m+8) * KPOS + n) =
                __floats2half2_rn(c[mt][nt][2]*SCALE, c[mt][nt][3]*SCALE);
        }
    }
    #undef CG_ISSUE
}

// ---------------- transpose+split V (fp16) ----------------
__global__ void transpose_v()
{
    __shared__ float sm[32][33];
    int bh = blockIdx.z;
    int j0 = blockIdx.x * 32, d0 = blockIdx.y * 32;
    int tx = threadIdx.x, ty = threadIdx.y;
    sm[ty][tx] = g_V[(size_t)bh*65536 + (size_t)(j0+ty)*64 + d0+tx];
    __syncthreads();
    float val = sm[tx][ty];
    __half hb = __float2half_rn(val);
    __half lb = __float2half_rn(val - __half2float(hb));
    unsigned short* dr = g_Vtsp + (size_t)bh*131072 + (size_t)(d0+ty)*2048;
    dr[j0+tx]        = __half_as_ushort(hb);
    dr[1024 + j0+tx] = __half_as_ushort(lb);
}

__global__ void lut_prep(const int* __restrict__ rp)
{
    int r = threadIdx.x;
    int bp = rp[(size_t)r * S];
    int bn = rp[r];
    #define CLIP(v) ((v) < 0 ? 0 : ((v) > 511 ? 511 : (v)))
    g_lutC[1023 + r] = (short)CLIP(bp + 256);
    g_lutC[1023 - r] = (short)CLIP(bn + 256);
    g_lutP[1023 + r] = (short)CLIP(256 - bn);
    g_lutP[1023 - r] = (short)CLIP(256 - bp);
    #undef CLIP
}

// ---------------- attn_logits (R16-validated, unchanged) ----------
#define AT_T0 0
#define AT_T1 34816
#define AT_Q  69632
#define AT_LC 71936
#define AT_LP 76032
#define AT_SMEM 80128
#define LGS_STRIDE 1028

__global__ void __launch_bounds__(256, 2) attn_logits(
    float* __restrict__ out_probs, float* __restrict__ out_logits)
{
    extern __shared__ char sm[];
    short* lutC = (short*)(sm + AT_LC);
    short* lutP = (short*)(sm + AT_LP);
    __shared__ float s_m[16][8];
    __shared__ float s_rowmax[16];
    __shared__ float s_red16[16][16];
    __shared__ float s_rinv[16];

    int it = blockIdx.x, bh = blockIdx.y;
    int i0 = it * 16;
    int t = threadIdx.x, wid = t >> 5, lid = t & 31;
    int wq = wid & 3, wbuf = wid >> 2;

    const __half* c2pB = g_c2pH + (size_t)bh * S * KPOS;
    const __half* p2cB = g_p2cH + (size_t)bh * S * KPOS;

    ((uint4*)(sm + AT_LC))[t] = ((const uint4*)g_lutC)[t];
    ((uint4*)(sm + AT_LP))[t] = ((const uint4*)g_lutP)[t];
    if (t < 128) {
        int row = t >> 3, off = t & 7;
        *(uint4*)(sm + AT_Q + row*144 + off*16) =
            *(const uint4*)(g_Qp + (((size_t)bh*1024 + i0 + row) << 6) + off*8);
    }

    {
        int row = t >> 1, part = t & 1;
        uint32_t dstb = smem_u32(sm) + AT_T0 + row*272 + part*128;
        const unsigned short* src = g_Ksp + (((size_t)bh*1024 + row) << 7) + part*64;
        #pragma unroll
        for (int q = 0; q < 8; q++) CP_ASYNC16(dstb + q*16, src + q*8);
        CP_COMMIT();
    }

    int rowA  = (lid & 7) + ((lid >> 3) & 1) * 8;
    int koffA = ((lid >> 4) & 1) * 16;
    int rowB  = (lid & 7) + ((lid >> 4) & 1) * 8;
    int koffB = ((lid >> 3) & 1) * 16;
    int r  = lid >> 2;
    int cc = 2 * (lid & 3);

    float lgr[8][2][4];
    float rmax2[2] = { -3.4e38f, -3.4e38f };
    uint32_t qbase = smem_u32(sm) + AT_Q;

    #pragma unroll
    for (int g = 0; g < 8; g++) {
        if (g < 7) {
            int row = t >> 1, part = t & 1;
            uint32_t dstb = smem_u32(sm) + ((g+1)&1 ? AT_T1 : AT_T0) + row*272 + part*128;
            const unsigned short* src = g_Ksp +
                (((size_t)bh*1024 + (g+1)*128 + row) << 7) + part*64;
            #pragma unroll
            for (int q = 0; q < 8; q++) CP_ASYNC16(dstb + q*16, src + q*8);
            CP_COMMIT();
            CP_WAIT1();
        } else {
            CP_WAIT0();
        }
        __syncthreads();

        uint32_t kbase = smem_u32(sm) + (g&1 ? AT_T1 : AT_T0) + wbuf*64*272;
        float c[2][4] = {{0,0,0,0},{0,0,0,0}};

        #pragma unroll
        for (int s = 0; s < 4; s++) {
            uint32_t ah[4], bhr[4], blr[4];
            uint32_t qa = qbase + rowA*144 + s*32 + koffA;
            LDMATRIX_X4(ah[0], ah[1], ah[2], ah[3], qa);
            uint32_t ba = kbase + (wq*16 + rowB)*272 + s*32 + koffB;
            LDMATRIX_X4(bhr[0], bhr[1], bhr[2], bhr[3], ba);
            LDMATRIX_X4(blr[0], blr[1], blr[2], blr[3], ba + 128);
            #pragma unroll
            for (int nt = 0; nt < 2; nt++) {
                uint32_t bhf[2] = { bhr[nt*2], bhr[nt*2+1] };
                uint32_t blf[2] = { blr[nt*2], blr[nt*2+1] };
                MMA_FP16(c[nt], ah, bhf);
                MMA_FP16(c[nt], ah, blf);
            }
        }

        int jt = 2*g + wbuf;
        #pragma unroll
        for (int nt = 0; nt < 2; nt++) {
            int jg = jt*64 + wq*16 + nt*8 + cc;
            #pragma unroll
            for (int e = 0; e < 4; e++) {
                int ig = i0 + r + (e >> 1) * 8;
                int j  = jg + (e & 1);
                int rel = ig - j + 1023;
                float l = c[nt][e] * SCALE
                        + __half2float(c2pB[((size_t)ig << 9) + lutC[rel]])
                        + __half2float(p2cB[((size_t)j  << 9) + lutP[rel]]);
                lgr[g][nt][e] = l;
                rmax2[e >> 1] = fmaxf(rmax2[e >> 1], l);
            }
        }
        __syncthreads();
    }

    #pragma unroll
    for (int e = 0; e < 2; e++) {
        float v = rmax2[e];
        v = fmaxf(v, __shfl_xor_sync(0xffffffff, v, 1));
        v = fmaxf(v, __shfl_xor_sync(0xffffffff, v, 2));
        if ((lid & 3) == 0) s_m[r + e*8][wid] = v;
    }
    __syncthreads();
    if (t < 16) {
        float m = s_m[t][0];
        #pragma unroll
        for (int x = 1; x < 8; x++) m = fmaxf(m, s_m[t][x]);
        s_rowmax[t] = m;
    }
    __syncthreads();

    float* lgs = (float*)sm;
    {
        float rmA = s_rowmax[r], rmB = s_rowmax[r + 8];
        #pragma unroll
        for (int g = 0; g < 8; g++) {
            int jt = 2*g + wbuf;
            #pragma unroll
            for (int nt = 0; nt < 2; nt++) {
                int jg = jt*64 + wq*16 + nt*8 + cc;
                *(float2*)&lgs[r*LGS_STRIDE + jg] =
                    make_float2(lgr[g][nt][0] - rmA, lgr[g][nt][1] - rmA);
                *(float2*)&lgs[(r+8)*LGS_STRIDE + jg] =
                    make_float2(lgr[g][nt][2] - rmB, lgr[g][nt][3] - rmB);
            }
        }
    }
    __syncthreads();

    int row = t >> 4, c0 = t & 15;
    float4* lrow  = (float4*)(lgs + row * LGS_STRIDE);
    float4* glrow = (float4*)(out_logits + ((size_t)bh * S + i0 + row) * S);
    float ssum = 0.f;
    #pragma unroll
    for (int c = 0; c < 16; c++) {
        int c4 = c0 + 16*c;
        float4 v = lrow[c4];
        glrow[c4] = v;
        float4 e;
        e.x = __expf(v.x); e.y = __expf(v.y);
        e.z = __expf(v.z); e.w = __expf(v.w);
        lrow[c4] = e;
        ssum += e.x + e.y + e.z + e.w;
    }
    s_red16[row][c0] = ssum;
    __syncthreads();
    if (t < 16) {
        float ssu = 0.f;
        #pragma unroll
        for (int x = 0; x < 16; x++) ssu += s_red16[t][x];
        s_rinv[t] = 1.0f / ssu;
    }
    __syncthreads();

    float inv = s_rinv[row];
    float4* gprow = (float4*)(out_probs + ((size_t)bh * S + i0 + row) * S);
    __half* prow = g_Pp + (((size_t)bh*1024 + i0 + row) << 10);
    #pragma unroll
    for (int c = 0; c < 16; c++) {
        int c4 = c0 + 16*c;
        float4 e = lrow[c4];
        e.x *= inv; e.y *= inv; e.z *= inv; e.w *= inv;
        gprow[c4] = e;
        __half2 p0 = __floats2half2_rn(e.x, e.y);
        __half2 p1 = __floats2half2_rn(e.z, e.w);
        *(uint2*)(prow + 4*c4) = make_uint2(
            ((uint32_t)__half_as_ushort(p0.y) << 16) | __half_as_ushort(p0.x),
            ((uint32_t)__half_as_ushort(p1.y) << 16) | __half_as_ushort(p1.x));
    }
}

// ---------------- ctx_gemm (R16-validated, unchanged) ----------
#define CX_STAGE 20480
#define CX_SMEM (2*CX_STAGE)

__global__ void __launch_bounds__(256) ctx_gemm(float* __restrict__ out_ctx)
{
    extern __shared__ char sm[];
    int m0 = blockIdx.x * 128, bh = blockIdx.y;
    int b = bh >> 4, h = bh & 15;
    const __half* A = g_Pp + ((size_t)bh << 20);
    const unsigned short* B = g_Vtsp + ((size_t)bh << 17);

    int t = threadIdx.x, wid = t >> 5, lid = t & 31;
    int wm = wid & 3, wn = wid >> 2;

    int rowA  = (lid & 7) + ((lid >> 3) & 1) * 8;
    int koffA = ((lid >> 4) & 1) * 16;
    int rowB  = (lid & 7) + ((lid >> 4) & 1) * 8;
    int koffB = ((lid >> 3) & 1) * 16;

    float c[2][4][4];
    #pragma unroll
    for (int i = 0; i < 2; i++)
        #pragma unroll
        for (int j = 0; j < 4; j++)
            #pragma unroll
            for (int e = 0; e < 4; e++) c[i][j][e] = 0.f;

    #define CX_ISSUE(stage, kt) do { \
        uint32_t sbase = smem_u32(sm) + (stage) * CX_STAGE; \
        _Pragma("unroll") \
        for (int q = 0; q < 2; q++) { \
            int idx = t + 256*q, row = idx >> 2, ch = idx & 3; \
            const __half* srcA = A + (size_t)(m0+row)*1024 + (kt)*32 + ch*8; \
            CP_ASYNC16(sbase + row*80 + ch*16, srcA); \
        } \
        _Pragma("unroll") \
        for (int q = 0; q < 2; q++) { \
            int idx = t + 256*q, part = idx >> 8, rem = idx & 255; \
            int row = rem >> 2, ch = rem & 3; \
            const unsigned short* srcB = B + (size_t)row*2048 + part*1024 + (kt)*32 + ch*8; \
            CP_ASYNC16(sbase + 10240 + part*5120 + row*80 + ch*16, srcB); \
        } \
        CP_COMMIT(); \
    } while (0)

    CX_ISSUE(0, 0);

    for (int kt = 0; kt < 32; kt++) {
        if (kt + 1 < 32) { CX_ISSUE((kt + 1) & 1, kt + 1); CP_WAIT1(); }
        else             { CP_WAIT0(); }
        __syncthreads();

        uint32_t aB = smem_u32(sm) + (kt & 1) * CX_STAGE;
        uint32_t bH = aB + 10240, bL = aB + 15360;

        #pragma unroll
        for (int s = 0; s < 2; s++) {
            uint32_t a[2][4], bh4[2][4], bl4[2][4];
            #pragma unroll
            for (int mt = 0; mt < 2; mt++) {
                uint32_t ro = (uint32_t)((wm*32 + mt*16 + rowA)*80 + s*32 + koffA);
                LDMATRIX_X4(a[mt][0], a[mt][1], a[mt][2], a[mt][3], aB + ro);
            }
            #pragma unroll
            for (int q = 0; q < 2; q++) {
                uint32_t ro = (uint32_t)((wn*32 + q*16 + rowB)*80 + s*32 + koffB);
                LDMATRIX_X4(bh4[q][0], bh4[q][1], bh4[q][2], bh4[q][3], bH + ro);
                LDMATRIX_X4(bl4[q][0], bl4[q][1], bl4[q][2], bl4[q][3], bL + ro);
            }
            #pragma unroll
            for (int mt = 0; mt < 2; mt++) {
                #pragma unroll
                for (int nt = 0; nt < 4; nt++) {
                    uint32_t bhf[2] = { bh4[nt>>1][(nt&1)*2], bh4[nt>>1][(nt&1)*2+1] };
                    uint32_t blf[2] = { bl4[nt>>1][(nt&1)*2], bl4[nt>>1][(nt&1)*2+1] };
                    MMA_FP16(c[mt][nt], a[mt], bhf);
                    MMA_FP16(c[mt][nt], a[mt], blf);
                }
            }
        }
        if (kt + 2 < 32) __syncthreads();
    }

    #pragma unroll
    for (int mt = 0; mt < 2; mt++) {
        #pragma unroll
        for (int nt = 0; nt < 4; nt++) {
            int m = m0 + wm*32 + mt*16 + (lid >> 2);
            int n = wn*32 + nt*8 + 2*(lid & 3);
            float* drow = out_ctx + ((size_t)(b*1024 + m))*1024 + h*64 + n;
            *(float2*)drow = make_float2(c[mt][nt][0], c[mt][nt][1]);
            *(float2*)(drow + (size_t)8*1024) = make_float2(c[mt][nt][2], c[mt][nt][3]);
        }
    }
    #undef CX_ISSUE
}

// ---------------- launch ----------------
extern "C" void kernel_launch(void* const* d_in, const int* in_sizes, int n_in,
                              void* d_out, int out_size)
{
    const float* hidden = (const float*)d_in[0];
    const int*   rp     = (const int*)  d_in[2];
    const float* rel    = (const float*)d_in[3];
    const float* Wq     = (const float*)d_in[4];
    const float* bq     = (const float*)d_in[5];
    const float* Wk     = (const float*)d_in[6];
    const float* bk     = (const float*)d_in[7];
    const float* Wv     = (const float*)d_in[8];
    const float* bv     = (const float*)d_in[9];

    float* out        = (float*)d_out;
    float* out_ctx    = out;
    float* out_probs  = out + (size_t)BB*S*HID;
    float* out_logits = out_probs + (size_t)BB*H*S*S;

    cudaFuncSetAttribute(gemm_fp16,
                         cudaFuncAttributeMaxDynamicSharedMemorySize, GF_SMEM);
    cudaFuncSetAttribute(cp_gemm,
                         cudaFuncAttributeMaxDynamicSharedMemorySize, CG_SMEM);
    cudaFuncSetAttribute(attn_logits,
                         cudaFuncAttributeMaxDynamicSharedMemorySize, AT_SMEM);
    cudaFuncSetAttribute(ctx_gemm,
                         cudaFuncAttributeMaxDynamicSharedMemorySize, CX_SMEM);

    __half* d_hidh; cudaGetSymbolAddress((void**)&d_hidh, g_hidh);
    __half* d_relh; cudaGetSymbolAddress((void**)&d_relh, g_relh);

    // launch index 3 (gemm_fp16 mode0) is the one ncu captures
    tofp16_wide<<<2048, 256>>>(hidden, d_hidh);                  // 0
    split_w3<<<3072, 256>>>(Wq, Wk, Wv);                         // 1
    tofp16_wide<<<512,  256>>>(rel,    d_relh);                  // 2
    gemm_fp16<<<dim3(16, 8, 3), 256, GF_SMEM>>>(bq, bk, bv, 0);  // 3 <- profiled
    lut_prep<<<1, 1024>>>(rp);                                   // 4
    gemm_fp16<<<dim3(4,  8, 2), 256, GF_SMEM>>>(bq, bk, bv, 1);  // 5
    transpose_v<<<dim3(32, 2, 32), dim3(32, 32)>>>();            // 6
    cp_gemm<<<dim3(8, 4, 64), 256, CG_SMEM>>>();                 // 7
    attn_logits<<<dim3(64, 32), 256, AT_SMEM>>>(out_probs, out_logits); // 8
    ctx_gemm<<<dim3(8, 32), 256, CX_SMEM>>>(out_ctx);                   // 9
}